// round 1
// baseline (speedup 1.0000x reference)
#include <cuda_runtime.h>
#include <math.h>

// Problem constants
#define BB   2
#define LS   2048
#define DM   1024
#define DIN  2048
#define DST  16
#define RDT  64
#define ML   (BB*LS)      // 4096 rows (b*LS + l)
#define DFF  (4*DM)       // 4096

static_assert((LS & (LS - 1)) == 0, "flip trick needs power-of-two L");

// ---------------- scratch (device globals; no allocation allowed) -----------
__device__ __align__(256) float g_xz  [2u * ML * 2 * DIN];  // [dir][ML][4096]
__device__ __align__(256) float g_xc  [2u * ML * DIN];      // [dir][ML][2048]
__device__ __align__(256) float g_xdbl[2u * ML * 96];       // [dir][ML][96]
__device__ __align__(256) float g_dt  [2u * ML * DIN];      // [dir][ML][2048]
__device__ __align__(256) float g_y   [2u * ML * DIN];      // [dir][ML][2048]
__device__ __align__(256) float g_ydir[2u * ML * DM];       // [dir][ML][1024] (unflipped)
__device__ __align__(256) float g_xsum[(size_t)ML * DM];
__device__ __align__(256) float g_ln  [(size_t)ML * DM];
__device__ __align__(256) float g_ff1 [(size_t)ML * DFF];

// ---------------- device helpers --------------------------------------------
__device__ __forceinline__ float siluf(float v) { return v / (1.f + expf(-v)); }
__device__ __forceinline__ float softplusf(float v) {
    return (v > 20.f) ? v : log1pf(expf(v));
}

// ---------------- generic tiled SGEMM: C[M,N] = A[M,K] * B[N,K]^T ------------
// 128x128x16 tiles, 256 threads, 8x8 per thread (2x2 quadrants of 4).
// act: 0=none, 1=silu(v+bias), 2=softplus(v+bias)
// flipA: read A rows with l -> L-1-l (within each batch of LS rows)
// flipC: write C rows with l -> L-1-l
__global__ __launch_bounds__(256)
void sgemm_kernel(const float* __restrict__ A, int lda,
                  const float* __restrict__ Bw, int ldb,
                  const float* __restrict__ bias,
                  const float* __restrict__ addsrc,
                  float* __restrict__ C, int ldc,
                  int M, int N, int K,
                  int act, int flipA, int flipC)
{
    __shared__ float As[16][132];
    __shared__ float Bs[16][132];

    const int tid = threadIdx.x;
    const int tx = tid & 15;        // 16 col groups
    const int ty = tid >> 4;        // 16 row groups
    const int rowBase = blockIdx.y * 128;
    const int colBase = blockIdx.x * 128;

    // loader mapping: each thread loads 8 elements (two float4) of a 128x16 tile
    const int lm = tid >> 1;            // 0..127
    const int lk = (tid & 1) * 8;       // 0 or 8

    int aRow = rowBase + lm;
    if (flipA) aRow ^= (LS - 1);
    const float* aPtr = A + (size_t)aRow * lda + lk;

    const int bRow = colBase + lm;
    const bool bValid = bRow < N;
    const float* bPtr = Bw + (size_t)bRow * ldb + lk;

    float acc[8][8];
    #pragma unroll
    for (int i = 0; i < 8; i++)
        #pragma unroll
        for (int j = 0; j < 8; j++) acc[i][j] = 0.f;

    for (int k0 = 0; k0 < K; k0 += 16) {
        float4 a0 = *(const float4*)(aPtr + k0);
        float4 a1 = *(const float4*)(aPtr + k0 + 4);
        float4 b0 = bValid ? *(const float4*)(bPtr + k0)     : make_float4(0,0,0,0);
        float4 b1 = bValid ? *(const float4*)(bPtr + k0 + 4) : make_float4(0,0,0,0);

        As[lk+0][lm] = a0.x; As[lk+1][lm] = a0.y; As[lk+2][lm] = a0.z; As[lk+3][lm] = a0.w;
        As[lk+4][lm] = a1.x; As[lk+5][lm] = a1.y; As[lk+6][lm] = a1.z; As[lk+7][lm] = a1.w;
        Bs[lk+0][lm] = b0.x; Bs[lk+1][lm] = b0.y; Bs[lk+2][lm] = b0.z; Bs[lk+3][lm] = b0.w;
        Bs[lk+4][lm] = b1.x; Bs[lk+5][lm] = b1.y; Bs[lk+6][lm] = b1.z; Bs[lk+7][lm] = b1.w;
        __syncthreads();

        #pragma unroll
        for (int kk = 0; kk < 16; kk++) {
            float4 ra0 = *(const float4*)&As[kk][ty * 4];
            float4 ra1 = *(const float4*)&As[kk][64 + ty * 4];
            float4 rb0 = *(const float4*)&Bs[kk][tx * 4];
            float4 rb1 = *(const float4*)&Bs[kk][64 + tx * 4];
            float ar[8] = {ra0.x, ra0.y, ra0.z, ra0.w, ra1.x, ra1.y, ra1.z, ra1.w};
            float br[8] = {rb0.x, rb0.y, rb0.z, rb0.w, rb1.x, rb1.y, rb1.z, rb1.w};
            #pragma unroll
            for (int i = 0; i < 8; i++)
                #pragma unroll
                for (int j = 0; j < 8; j++)
                    acc[i][j] = fmaf(ar[i], br[j], acc[i][j]);
        }
        __syncthreads();
    }

    #pragma unroll
    for (int i = 0; i < 8; i++) {
        int r = rowBase + ((i < 4) ? (ty * 4 + i) : (64 + ty * 4 + i - 4));
        int rw = flipC ? (r ^ (LS - 1)) : r;
        #pragma unroll
        for (int j = 0; j < 8; j++) {
            int c = colBase + ((j < 4) ? (tx * 4 + j) : (64 + tx * 4 + j - 4));
            if (c < N) {
                float v = acc[i][j];
                if (bias) v += bias[c];
                if (act == 1)      v = siluf(v);
                else if (act == 2) v = softplusf(v);
                if (addsrc) v += addsrc[(size_t)rw * ldc + c];
                C[(size_t)rw * ldc + c] = v;
            }
        }
    }
}

// ---------------- depthwise causal conv (k=4, left pad 3) + bias + silu -----
__global__ void conv_kernel(const float* __restrict__ xz,  // [ML,4096] (xi = first 2048)
                            const float* __restrict__ cw,  // [DIN,4]
                            const float* __restrict__ cb,  // [DIN]
                            float* __restrict__ xc)        // [ML,DIN]
{
    int idx = blockIdx.x * blockDim.x + threadIdx.x;
    if (idx >= ML * DIN) return;
    int c = idx & (DIN - 1);
    int r = idx / DIN;            // b*LS + l
    int l = r & (LS - 1);
    int b = r / LS;
    float acc = cb[c];
    float w0 = cw[c * 4 + 0], w1 = cw[c * 4 + 1], w2 = cw[c * 4 + 2], w3 = cw[c * 4 + 3];
    #pragma unroll
    for (int k = 0; k < 4; k++) {
        int lp = l - 3 + k;
        if (lp >= 0) {
            float w = (k == 0) ? w0 : (k == 1) ? w1 : (k == 2) ? w2 : w3;
            acc += xz[((size_t)(b * LS + lp)) * (2 * DIN) + c] * w;
        }
    }
    xc[idx] = siluf(acc);
}

// ---------------- selective scan: 16 lanes per (b,d) row, 2 rows per warp ---
__global__ void scan_kernel(const float* __restrict__ dt,    // [ML,DIN]
                            const float* __restrict__ xc,    // [ML,DIN]
                            const float* __restrict__ xdbl,  // [ML,96]
                            const float* __restrict__ xz,    // [ML,4096] (z = cols 2048..)
                            const float* __restrict__ A_log, // [DIN,16]
                            const float* __restrict__ Dp,    // [DIN]
                            float* __restrict__ yout)        // [ML,DIN]
{
    int gwarp = (blockIdx.x * blockDim.x + threadIdx.x) >> 5;
    int lane = threadIdx.x & 31;
    int half = lane >> 4;
    int s = lane & 15;
    int row = gwarp * 2 + half;          // 0 .. BB*DIN-1
    if (row >= BB * DIN) return;
    int b = row / DIN;
    int d = row % DIN;

    float Av = -expf(A_log[d * DST + s]);
    float Dd = Dp[d];
    float h = 0.f;

    size_t base = (size_t)b * LS;
    for (int l = 0; l < LS; l++) {
        size_t blo = base + l;
        float dtv = dt[blo * DIN + d];
        float uv  = xc[blo * DIN + d];
        float Bv  = xdbl[blo * 96 + RDT + s];
        float Cv  = xdbl[blo * 96 + RDT + DST + s];
        h = h * expf(dtv * Av) + dtv * uv * Bv;
        float y = h * Cv;
        y += __shfl_xor_sync(0xffffffffu, y, 8);
        y += __shfl_xor_sync(0xffffffffu, y, 4);
        y += __shfl_xor_sync(0xffffffffu, y, 2);
        y += __shfl_xor_sync(0xffffffffu, y, 1);
        if (s == 0) {
            float z = xz[blo * (2 * DIN) + DIN + d];
            yout[blo * DIN + d] = (y + uv * Dd) * siluf(z);
        }
    }
}

// ---------------- residual combine: xsum = x + 0.5*(yf + yb) ----------------
__global__ void residual_kernel(const float* __restrict__ x,
                                const float* __restrict__ y0,
                                const float* __restrict__ y1,
                                float* __restrict__ xsum)
{
    int i = blockIdx.x * blockDim.x + threadIdx.x;
    int n = ML * DM / 4;
    if (i >= n) return;
    float4 xv = ((const float4*)x)[i];
    float4 a = ((const float4*)y0)[i];
    float4 b = ((const float4*)y1)[i];
    float4 o;
    o.x = xv.x + 0.5f * (a.x + b.x);
    o.y = xv.y + 0.5f * (a.y + b.y);
    o.z = xv.z + 0.5f * (a.z + b.z);
    o.w = xv.w + 0.5f * (a.w + b.w);
    ((float4*)xsum)[i] = o;
}

// ---------------- layernorm over last dim (1024), block per row -------------
__global__ void ln_kernel(const float* __restrict__ xin,
                          const float* __restrict__ g,
                          const float* __restrict__ bta,
                          float* __restrict__ out)
{
    int row = blockIdx.x;
    const float4* xr = (const float4*)(xin + (size_t)row * DM);
    float4 v = xr[threadIdx.x];
    float s  = v.x + v.y + v.z + v.w;
    float sq = v.x*v.x + v.y*v.y + v.z*v.z + v.w*v.w;

    #pragma unroll
    for (int o = 16; o >= 1; o >>= 1) {
        s  += __shfl_xor_sync(0xffffffffu, s, o);
        sq += __shfl_xor_sync(0xffffffffu, sq, o);
    }
    __shared__ float ss[8], ssq[8];
    int warp = threadIdx.x >> 5, lane = threadIdx.x & 31;
    if (lane == 0) { ss[warp] = s; ssq[warp] = sq; }
    __syncthreads();
    __shared__ float sh_mean, sh_inv;
    if (threadIdx.x == 0) {
        float ts = 0.f, tq = 0.f;
        #pragma unroll
        for (int w = 0; w < 8; w++) { ts += ss[w]; tq += ssq[w]; }
        float mean = ts / DM;
        float var = tq / DM - mean * mean;
        sh_mean = mean;
        sh_inv = rsqrtf(var + 1e-5f);
    }
    __syncthreads();
    float mean = sh_mean, inv = sh_inv;
    float4 gv = ((const float4*)g)[threadIdx.x];
    float4 bv = ((const float4*)bta)[threadIdx.x];
    float4 o;
    o.x = (v.x - mean) * inv * gv.x + bv.x;
    o.y = (v.y - mean) * inv * gv.y + bv.y;
    o.z = (v.z - mean) * inv * gv.z + bv.z;
    o.w = (v.w - mean) * inv * gv.w + bv.w;
    ((float4*)(out + (size_t)row * DM))[threadIdx.x] = o;
}

// ---------------- host orchestration ----------------------------------------
extern "C" void kernel_launch(void* const* d_in, const int* in_sizes, int n_in,
                              void* d_out, int out_size)
{
    (void)in_sizes; (void)n_in; (void)out_size;

    const float* x = (const float*)d_in[0];
    const float* in_w[2]   = { (const float*)d_in[1],  (const float*)d_in[10] };
    const float* conv_w[2] = { (const float*)d_in[2],  (const float*)d_in[11] };
    const float* conv_b[2] = { (const float*)d_in[3],  (const float*)d_in[12] };
    const float* x_w[2]    = { (const float*)d_in[4],  (const float*)d_in[13] };
    const float* dt_w[2]   = { (const float*)d_in[5],  (const float*)d_in[14] };
    const float* dt_b[2]   = { (const float*)d_in[6],  (const float*)d_in[15] };
    const float* A_log[2]  = { (const float*)d_in[7],  (const float*)d_in[16] };
    const float* Dp[2]     = { (const float*)d_in[8],  (const float*)d_in[17] };
    const float* out_w[2]  = { (const float*)d_in[9],  (const float*)d_in[18] };
    const float* ff_ln_g = (const float*)d_in[19];
    const float* ff_ln_b = (const float*)d_in[20];
    const float* ff_w1   = (const float*)d_in[21];
    const float* ff_b1   = (const float*)d_in[22];
    const float* ff_w2   = (const float*)d_in[23];
    const float* ff_b2   = (const float*)d_in[24];

    float *xz, *xc, *xdbl, *dtb, *yb, *ydir, *xsum, *lnb, *ff1;
    cudaGetSymbolAddress((void**)&xz,   g_xz);
    cudaGetSymbolAddress((void**)&xc,   g_xc);
    cudaGetSymbolAddress((void**)&xdbl, g_xdbl);
    cudaGetSymbolAddress((void**)&dtb,  g_dt);
    cudaGetSymbolAddress((void**)&yb,   g_y);
    cudaGetSymbolAddress((void**)&ydir, g_ydir);
    cudaGetSymbolAddress((void**)&xsum, g_xsum);
    cudaGetSymbolAddress((void**)&lnb,  g_ln);
    cudaGetSymbolAddress((void**)&ff1,  g_ff1);

    const size_t szXZ   = (size_t)ML * 2 * DIN;
    const size_t szXC   = (size_t)ML * DIN;
    const size_t szXDBL = (size_t)ML * 96;
    const size_t szYDIR = (size_t)ML * DM;

    dim3 blk(256);

    for (int dir = 0; dir < 2; dir++) {
        float* xz_d   = xz   + dir * szXZ;
        float* xc_d   = xc   + dir * szXC;
        float* xdbl_d = xdbl + dir * szXDBL;
        float* dt_d   = dtb  + dir * szXC;
        float* y_d    = yb   + dir * szXC;
        float* ydir_d = ydir + dir * szYDIR;

        // in-proj: xz = x @ in_w^T  (M=4096, N=4096, K=1024), flip A rows for bwd
        sgemm_kernel<<<dim3(4096/128, 4096/128), blk>>>(
            x, DM, in_w[dir], DM, nullptr, nullptr,
            xz_d, 2*DIN, ML, 2*DIN, DM, 0, dir, 0);

        // causal depthwise conv + silu
        conv_kernel<<<(ML*DIN + 255)/256, blk>>>(xz_d, conv_w[dir], conv_b[dir], xc_d);

        // xdbl = xc @ x_w^T  (M=4096, N=96, K=2048)
        sgemm_kernel<<<dim3(1, 4096/128), blk>>>(
            xc_d, DIN, x_w[dir], DIN, nullptr, nullptr,
            xdbl_d, 96, ML, 96, DIN, 0, 0, 0);

        // dt = softplus(xdbl[:, :64] @ dt_w^T + dt_b)  (M=4096, N=2048, K=64)
        sgemm_kernel<<<dim3(2048/128, 4096/128), blk>>>(
            xdbl_d, 96, dt_w[dir], RDT, dt_b[dir], nullptr,
            dt_d, DIN, ML, DIN, RDT, 2, 0, 0);

        // selective scan + skip(D) + silu(z) gate -> y
        scan_kernel<<<256, blk>>>(dt_d, xc_d, xdbl_d, xz_d, A_log[dir], Dp[dir], y_d);

        // out-proj: ydir = y @ out_w^T  (M=4096, N=1024, K=2048), flip C rows for bwd
        sgemm_kernel<<<dim3(1024/128, 4096/128), blk>>>(
            y_d, DIN, out_w[dir], DIN, nullptr, nullptr,
            ydir_d, DM, ML, DM, DIN, 0, 0, dir);
    }

    // xsum = x + 0.5*(y_f + y_b)
    residual_kernel<<<(ML*DM/4 + 255)/256, blk>>>(x, ydir, ydir + szYDIR, xsum);

    // layernorm
    ln_kernel<<<ML, blk>>>(xsum, ff_ln_g, ff_ln_b, lnb);

    // ff1 = silu(ln @ ff_w1^T + b1)  (M=4096, N=4096, K=1024)
    sgemm_kernel<<<dim3(4096/128, 4096/128), blk>>>(
        lnb, DM, ff_w1, DM, ff_b1, nullptr,
        ff1, DFF, ML, DFF, DM, 1, 0, 0);

    // out = xsum + (ff1 @ ff_w2^T + b2)  (M=4096, N=1024, K=4096)
    sgemm_kernel<<<dim3(1024/128, 4096/128), blk>>>(
        ff1, DFF, ff_w2, DFF, ff_b2, xsum,
        (float*)d_out, DM, ML, DM, DFF, 0, 0, 0);
}

// round 3
// speedup vs baseline: 1.2626x; 1.2626x over previous
#include <cuda_runtime.h>
#include <cuda_bf16.h>
#include <math.h>
#include <stdint.h>

// Problem constants
#define BB   2
#define LS   2048
#define DM   1024
#define DIN  2048
#define DST  16
#define RDT  64
#define ML   (BB*LS)      // 4096 rows
#define DFF  (4*DM)       // 4096

// ---------------- scratch (device globals) -----------------------------------
__device__ __align__(256) float g_xz  [2u * ML * 2 * DIN];
__device__ __align__(256) float g_xc  [2u * ML * DIN];
__device__ __align__(256) float g_xdbl[2u * ML * 96];
__device__ __align__(256) float g_dt  [2u * ML * DIN];
__device__ __align__(256) float g_y   [2u * ML * DIN];
__device__ __align__(256) float g_ydir[2u * ML * DM];
__device__ __align__(256) float g_xsum[(size_t)ML * DM];
__device__ __align__(256) float g_ln  [(size_t)ML * DM];
__device__ __align__(256) float g_ff1 [(size_t)ML * DFF];

// ---------------- helpers ------------------------------------------------------
__device__ __forceinline__ float siluf(float v) { return v / (1.f + expf(-v)); }
__device__ __forceinline__ float softplusf(float v) { return (v > 20.f) ? v : log1pf(expf(v)); }

// convert 8 fp32 -> 8 bf16 hi + 8 bf16 lo (packed as uint4 each)
__device__ __forceinline__ void cv8(float4 v0, float4 v1, uint4& h, uint4& l) {
    float fa[8] = {v0.x, v0.y, v0.z, v0.w, v1.x, v1.y, v1.z, v1.w};
    uint32_t hh[4], ll[4];
    #pragma unroll
    for (int i = 0; i < 4; i++) {
        __nv_bfloat16 h0 = __float2bfloat16(fa[2*i]);
        __nv_bfloat16 h1 = __float2bfloat16(fa[2*i+1]);
        float r0 = fa[2*i]   - __bfloat162float(h0);
        float r1 = fa[2*i+1] - __bfloat162float(h1);
        __nv_bfloat16 l0 = __float2bfloat16(r0);
        __nv_bfloat16 l1 = __float2bfloat16(r1);
        hh[i] = (uint32_t)__bfloat16_as_ushort(h0) | ((uint32_t)__bfloat16_as_ushort(h1) << 16);
        ll[i] = (uint32_t)__bfloat16_as_ushort(l0) | ((uint32_t)__bfloat16_as_ushort(l1) << 16);
    }
    h = make_uint4(hh[0], hh[1], hh[2], hh[3]);
    l = make_uint4(ll[0], ll[1], ll[2], ll[3]);
}

#define LDSM4(r0, r1, r2, r3, addr) \
    asm volatile("ldmatrix.sync.aligned.m8n8.x4.shared.b16 {%0,%1,%2,%3}, [%4];" \
        : "=r"(r0), "=r"(r1), "=r"(r2), "=r"(r3) : "r"(addr))

#define MMA16816(d, a, b0, b1) \
    asm volatile("mma.sync.aligned.m16n8k16.row.col.f32.bf16.bf16.f32 " \
        "{%0,%1,%2,%3}, {%4,%5,%6,%7}, {%8,%9}, {%0,%1,%2,%3};" \
        : "+f"((d)[0]), "+f"((d)[1]), "+f"((d)[2]), "+f"((d)[3]) \
        : "r"((a)[0]), "r"((a)[1]), "r"((a)[2]), "r"((a)[3]), "r"(b0), "r"(b1))

// ---------------- split-bf16 tensor-core GEMM: C[M,N] = A[M,K] * B[N,K]^T ------
// 128x128x32 tiles, 256 thr, 8 warps (2Mx4N), warp tile 64x32, 3 mma products.
#define SMS 40                 // padded row length in bf16 (80 bytes)
#define TILE_B (128 * SMS * 2) // 10240 bytes per [128][40] bf16 array
#define STAGE  (4 * TILE_B)    // Ahi, Alo, Bhi, Blo
#define DSMEM  (2 * STAGE)     // double buffered: 81920 bytes

__global__ __launch_bounds__(256)
void mma_gemm(const float* __restrict__ A, int lda,
              const float* __restrict__ Bw, int ldb,
              const float* __restrict__ bias,
              const float* __restrict__ addsrc,
              float* __restrict__ C, int ldc,
              int K, int act, int flipA, int flipC)
{
    extern __shared__ char sm[];
    const int tid  = threadIdx.x;
    const int lane = tid & 31;
    const int wid  = tid >> 5;
    const int wm   = wid >> 2;   // 0..1
    const int wn   = wid & 3;    // 0..3
    const int rowBase = blockIdx.y * 128;
    const int colBase = blockIdx.x * 128;
    const uint32_t smb = (uint32_t)__cvta_generic_to_shared(sm);

    // global loaders: thread t -> row t>>1, 16 cols starting at (t&1)*16
    int aRow = rowBase + (tid >> 1);
    if (flipA) aRow ^= (LS - 1);
    const float* pA = A  + (size_t)aRow * lda + (tid & 1) * 16;
    const float* pB = Bw + (size_t)(colBase + (tid >> 1)) * ldb + (tid & 1) * 16;
    const uint32_t stsOff = (uint32_t)(tid >> 1) * (SMS * 2) + (uint32_t)(tid & 1) * 32;

    // ldmatrix fragment base offsets (byte offsets within a [128][40] bf16 array)
    const uint32_t aFragOff =
        (uint32_t)(wm * 64 + (lane & 7) + ((lane >> 3) & 1) * 8) * (SMS * 2) +
        (uint32_t)(lane >> 4) * 16;
    const uint32_t bFragOff =
        (uint32_t)(wn * 32 + (lane & 7) + ((lane >> 4) & 1) * 8) * (SMS * 2) +
        (uint32_t)((lane >> 3) & 1) * 16;

    float acc[16][4];
    #pragma unroll
    for (int i = 0; i < 16; i++)
        #pragma unroll
        for (int j = 0; j < 4; j++) acc[i][j] = 0.f;

    const int nk = K / 32;
    float4 ra[4], rb[4];
    // prefetch tile 0
    ra[0] = *(const float4*)(pA);     ra[1] = *(const float4*)(pA + 4);
    ra[2] = *(const float4*)(pA + 8); ra[3] = *(const float4*)(pA + 12);
    rb[0] = *(const float4*)(pB);     rb[1] = *(const float4*)(pB + 4);
    rb[2] = *(const float4*)(pB + 8); rb[3] = *(const float4*)(pB + 12);

    for (int kt = 0; kt < nk; kt++) {
        // stage current prefetch into smem (split hi/lo)
        char* st = sm + (size_t)(kt & 1) * STAGE;
        {
            uint4 h, l;
            cv8(ra[0], ra[1], h, l);
            *(uint4*)(st + 0 * TILE_B + stsOff)      = h;
            *(uint4*)(st + 1 * TILE_B + stsOff)      = l;
            cv8(ra[2], ra[3], h, l);
            *(uint4*)(st + 0 * TILE_B + stsOff + 16) = h;
            *(uint4*)(st + 1 * TILE_B + stsOff + 16) = l;
            cv8(rb[0], rb[1], h, l);
            *(uint4*)(st + 2 * TILE_B + stsOff)      = h;
            *(uint4*)(st + 3 * TILE_B + stsOff)      = l;
            cv8(rb[2], rb[3], h, l);
            *(uint4*)(st + 2 * TILE_B + stsOff + 16) = h;
            *(uint4*)(st + 3 * TILE_B + stsOff + 16) = l;
        }
        __syncthreads();

        if (kt + 1 < nk) {
            const float* a = pA + (size_t)(kt + 1) * 32;
            const float* b = pB + (size_t)(kt + 1) * 32;
            ra[0] = *(const float4*)(a);     ra[1] = *(const float4*)(a + 4);
            ra[2] = *(const float4*)(a + 8); ra[3] = *(const float4*)(a + 12);
            rb[0] = *(const float4*)(b);     rb[1] = *(const float4*)(b + 4);
            rb[2] = *(const float4*)(b + 8); rb[3] = *(const float4*)(b + 12);
        }

        const uint32_t base = smb + (uint32_t)(kt & 1) * STAGE;
        #pragma unroll
        for (int ks = 0; ks < 2; ks++) {
            uint32_t aH[4][4], aL[4][4], bH[2][4], bL[2][4];
            const uint32_t aAddr = base + aFragOff + (uint32_t)ks * 32;
            const uint32_t bAddr = base + 2 * TILE_B + bFragOff + (uint32_t)ks * 32;
            #pragma unroll
            for (int i = 0; i < 4; i++)
                LDSM4(aH[i][0], aH[i][1], aH[i][2], aH[i][3],
                      aAddr + (uint32_t)i * 16 * (SMS * 2));
            #pragma unroll
            for (int p = 0; p < 2; p++)
                LDSM4(bH[p][0], bH[p][1], bH[p][2], bH[p][3],
                      bAddr + (uint32_t)p * 16 * (SMS * 2));
            // hi*hi
            #pragma unroll
            for (int i = 0; i < 4; i++)
                #pragma unroll
                for (int nt = 0; nt < 4; nt++)
                    MMA16816(acc[i*4+nt], aH[i], bH[nt>>1][(nt&1)*2], bH[nt>>1][(nt&1)*2+1]);
            // lo*hi
            #pragma unroll
            for (int i = 0; i < 4; i++)
                LDSM4(aL[i][0], aL[i][1], aL[i][2], aL[i][3],
                      aAddr + TILE_B + (uint32_t)i * 16 * (SMS * 2));
            #pragma unroll
            for (int i = 0; i < 4; i++)
                #pragma unroll
                for (int nt = 0; nt < 4; nt++)
                    MMA16816(acc[i*4+nt], aL[i], bH[nt>>1][(nt&1)*2], bH[nt>>1][(nt&1)*2+1]);
            // hi*lo
            #pragma unroll
            for (int p = 0; p < 2; p++)
                LDSM4(bL[p][0], bL[p][1], bL[p][2], bL[p][3],
                      bAddr + TILE_B + (uint32_t)p * 16 * (SMS * 2));
            #pragma unroll
            for (int i = 0; i < 4; i++)
                #pragma unroll
                for (int nt = 0; nt < 4; nt++)
                    MMA16816(acc[i*4+nt], aH[i], bL[nt>>1][(nt&1)*2], bL[nt>>1][(nt&1)*2+1]);
        }
        __syncthreads();
    }

    // epilogue straight from registers
    const int erow  = wm * 64 + (lane >> 2);
    const int ecol0 = wn * 32 + (lane & 3) * 2;
    #pragma unroll
    for (int i = 0; i < 4; i++) {
        int r0 = rowBase + erow + i * 16;
        int r1 = r0 + 8;
        int rw0 = flipC ? (r0 ^ (LS - 1)) : r0;
        int rw1 = flipC ? (r1 ^ (LS - 1)) : r1;
        #pragma unroll
        for (int nt = 0; nt < 4; nt++) {
            int c = colBase + ecol0 + nt * 8;
            float v0 = acc[i*4+nt][0], v1 = acc[i*4+nt][1];
            float v2 = acc[i*4+nt][2], v3 = acc[i*4+nt][3];
            if (bias) {
                float b0 = __ldg(&bias[c]), b1 = __ldg(&bias[c+1]);
                v0 += b0; v1 += b1; v2 += b0; v3 += b1;
            }
            if (act == 1) { v0 = siluf(v0); v1 = siluf(v1); v2 = siluf(v2); v3 = siluf(v3); }
            else if (act == 2) { v0 = softplusf(v0); v1 = softplusf(v1); v2 = softplusf(v2); v3 = softplusf(v3); }
            if (addsrc) {
                v0 += addsrc[(size_t)rw0 * ldc + c];
                v1 += addsrc[(size_t)rw0 * ldc + c + 1];
                v2 += addsrc[(size_t)rw1 * ldc + c];
                v3 += addsrc[(size_t)rw1 * ldc + c + 1];
            }
            float2 lo2 = make_float2(v0, v1);
            float2 hi2 = make_float2(v2, v3);
            *(float2*)&C[(size_t)rw0 * ldc + c] = lo2;
            *(float2*)&C[(size_t)rw1 * ldc + c] = hi2;
        }
    }
}

// ---------------- fp32 SGEMM (small GEMMs: xdbl, dt) ---------------------------
__global__ __launch_bounds__(256)
void sgemm_kernel(const float* __restrict__ A, int lda,
                  const float* __restrict__ Bw, int ldb,
                  const float* __restrict__ bias,
                  const float* __restrict__ addsrc,
                  float* __restrict__ C, int ldc,
                  int M, int N, int K,
                  int act, int flipA, int flipC)
{
    __shared__ float As[16][132];
    __shared__ float Bs[16][132];

    const int tid = threadIdx.x;
    const int tx = tid & 15;
    const int ty = tid >> 4;
    const int rowBase = blockIdx.y * 128;
    const int colBase = blockIdx.x * 128;

    const int lm = tid >> 1;
    const int lk = (tid & 1) * 8;

    int aRow = rowBase + lm;
    if (flipA) aRow ^= (LS - 1);
    const float* aPtr = A + (size_t)aRow * lda + lk;

    const int bRow = colBase + lm;
    const bool bValid = bRow < N;
    const float* bPtr = Bw + (size_t)bRow * ldb + lk;

    float acc[8][8];
    #pragma unroll
    for (int i = 0; i < 8; i++)
        #pragma unroll
        for (int j = 0; j < 8; j++) acc[i][j] = 0.f;

    for (int k0 = 0; k0 < K; k0 += 16) {
        float4 a0 = *(const float4*)(aPtr + k0);
        float4 a1 = *(const float4*)(aPtr + k0 + 4);
        float4 b0 = bValid ? *(const float4*)(bPtr + k0)     : make_float4(0,0,0,0);
        float4 b1 = bValid ? *(const float4*)(bPtr + k0 + 4) : make_float4(0,0,0,0);

        As[lk+0][lm] = a0.x; As[lk+1][lm] = a0.y; As[lk+2][lm] = a0.z; As[lk+3][lm] = a0.w;
        As[lk+4][lm] = a1.x; As[lk+5][lm] = a1.y; As[lk+6][lm] = a1.z; As[lk+7][lm] = a1.w;
        Bs[lk+0][lm] = b0.x; Bs[lk+1][lm] = b0.y; Bs[lk+2][lm] = b0.z; Bs[lk+3][lm] = b0.w;
        Bs[lk+4][lm] = b1.x; Bs[lk+5][lm] = b1.y; Bs[lk+6][lm] = b1.z; Bs[lk+7][lm] = b1.w;
        __syncthreads();

        #pragma unroll
        for (int kk = 0; kk < 16; kk++) {
            float4 ra0 = *(const float4*)&As[kk][ty * 4];
            float4 ra1 = *(const float4*)&As[kk][64 + ty * 4];
            float4 rb0 = *(const float4*)&Bs[kk][tx * 4];
            float4 rb1 = *(const float4*)&Bs[kk][64 + tx * 4];
            float ar[8] = {ra0.x, ra0.y, ra0.z, ra0.w, ra1.x, ra1.y, ra1.z, ra1.w};
            float br[8] = {rb0.x, rb0.y, rb0.z, rb0.w, rb1.x, rb1.y, rb1.z, rb1.w};
            #pragma unroll
            for (int i = 0; i < 8; i++)
                #pragma unroll
                for (int j = 0; j < 8; j++)
                    acc[i][j] = fmaf(ar[i], br[j], acc[i][j]);
        }
        __syncthreads();
    }

    #pragma unroll
    for (int i = 0; i < 8; i++) {
        int r = rowBase + ((i < 4) ? (ty * 4 + i) : (64 + ty * 4 + i - 4));
        int rw = flipC ? (r ^ (LS - 1)) : r;
        #pragma unroll
        for (int j = 0; j < 8; j++) {
            int c = colBase + ((j < 4) ? (tx * 4 + j) : (64 + tx * 4 + j - 4));
            if (c < N) {
                float v = acc[i][j];
                if (bias) v += bias[c];
                if (act == 1)      v = siluf(v);
                else if (act == 2) v = softplusf(v);
                if (addsrc) v += addsrc[(size_t)rw * ldc + c];
                C[(size_t)rw * ldc + c] = v;
            }
        }
    }
}

// ---------------- depthwise causal conv (k=4) + bias + silu --------------------
__global__ void conv_kernel(const float* __restrict__ xz,
                            const float* __restrict__ cw,
                            const float* __restrict__ cb,
                            float* __restrict__ xc)
{
    int idx = blockIdx.x * blockDim.x + threadIdx.x;
    if (idx >= ML * DIN) return;
    int c = idx & (DIN - 1);
    int r = idx / DIN;
    int l = r & (LS - 1);
    int b = r / LS;
    float acc = cb[c];
    float w0 = cw[c * 4 + 0], w1 = cw[c * 4 + 1], w2 = cw[c * 4 + 2], w3 = cw[c * 4 + 3];
    #pragma unroll
    for (int k = 0; k < 4; k++) {
        int lp = l - 3 + k;
        if (lp >= 0) {
            float w = (k == 0) ? w0 : (k == 1) ? w1 : (k == 2) ? w2 : w3;
            acc += xz[((size_t)(b * LS + lp)) * (2 * DIN) + c] * w;
        }
    }
    xc[idx] = siluf(acc);
}

// ---------------- selective scan -------------------------------------------------
__global__ void scan_kernel(const float* __restrict__ dt,
                            const float* __restrict__ xc,
                            const float* __restrict__ xdbl,
                            const float* __restrict__ xz,
                            const float* __restrict__ A_log,
                            const float* __restrict__ Dp,
                            float* __restrict__ yout)
{
    int gwarp = (blockIdx.x * blockDim.x + threadIdx.x) >> 5;
    int lane = threadIdx.x & 31;
    int half = lane >> 4;
    int s = lane & 15;
    int row = gwarp * 2 + half;
    if (row >= BB * DIN) return;
    int b = row / DIN;
    int d = row % DIN;

    float Av = -expf(A_log[d * DST + s]);
    float Dd = Dp[d];
    float h = 0.f;

    size_t base = (size_t)b * LS;
    for (int l = 0; l < LS; l++) {
        size_t blo = base + l;
        float dtv = dt[blo * DIN + d];
        float uv  = xc[blo * DIN + d];
        float Bv  = xdbl[blo * 96 + RDT + s];
        float Cv  = xdbl[blo * 96 + RDT + DST + s];
        h = h * expf(dtv * Av) + dtv * uv * Bv;
        float y = h * Cv;
        y += __shfl_xor_sync(0xffffffffu, y, 8);
        y += __shfl_xor_sync(0xffffffffu, y, 4);
        y += __shfl_xor_sync(0xffffffffu, y, 2);
        y += __shfl_xor_sync(0xffffffffu, y, 1);
        if (s == 0) {
            float z = xz[blo * (2 * DIN) + DIN + d];
            yout[blo * DIN + d] = (y + uv * Dd) * siluf(z);
        }
    }
}

// ---------------- residual combine -----------------------------------------------
__global__ void residual_kernel(const float* __restrict__ x,
                                const float* __restrict__ y0,
                                const float* __restrict__ y1,
                                float* __restrict__ xsum)
{
    int i = blockIdx.x * blockDim.x + threadIdx.x;
    int n = ML * DM / 4;
    if (i >= n) return;
    float4 xv = ((const float4*)x)[i];
    float4 a = ((const float4*)y0)[i];
    float4 b = ((const float4*)y1)[i];
    float4 o;
    o.x = xv.x + 0.5f * (a.x + b.x);
    o.y = xv.y + 0.5f * (a.y + b.y);
    o.z = xv.z + 0.5f * (a.z + b.z);
    o.w = xv.w + 0.5f * (a.w + b.w);
    ((float4*)xsum)[i] = o;
}

// ---------------- layernorm over last dim (1024) ----------------------------------
__global__ void ln_kernel(const float* __restrict__ xin,
                          const float* __restrict__ g,
                          const float* __restrict__ bta,
                          float* __restrict__ out)
{
    int row = blockIdx.x;
    const float4* xr = (const float4*)(xin + (size_t)row * DM);
    float4 v = xr[threadIdx.x];
    float s  = v.x + v.y + v.z + v.w;
    float sq = v.x*v.x + v.y*v.y + v.z*v.z + v.w*v.w;

    #pragma unroll
    for (int o = 16; o >= 1; o >>= 1) {
        s  += __shfl_xor_sync(0xffffffffu, s, o);
        sq += __shfl_xor_sync(0xffffffffu, sq, o);
    }
    __shared__ float ss[8], ssq[8];
    int warp = threadIdx.x >> 5, lane = threadIdx.x & 31;
    if (lane == 0) { ss[warp] = s; ssq[warp] = sq; }
    __syncthreads();
    __shared__ float sh_mean, sh_inv;
    if (threadIdx.x == 0) {
        float ts = 0.f, tq = 0.f;
        #pragma unroll
        for (int w = 0; w < 8; w++) { ts += ss[w]; tq += ssq[w]; }
        float mean = ts / DM;
        float var = tq / DM - mean * mean;
        sh_mean = mean;
        sh_inv = rsqrtf(var + 1e-5f);
    }
    __syncthreads();
    float mean = sh_mean, inv = sh_inv;
    float4 gv = ((const float4*)g)[threadIdx.x];
    float4 bv = ((const float4*)bta)[threadIdx.x];
    float4 o;
    o.x = (v.x - mean) * inv * gv.x + bv.x;
    o.y = (v.y - mean) * inv * gv.y + bv.y;
    o.z = (v.z - mean) * inv * gv.z + bv.z;
    o.w = (v.w - mean) * inv * gv.w + bv.w;
    ((float4*)(out + (size_t)row * DM))[threadIdx.x] = o;
}

// ---------------- host orchestration ----------------------------------------------
extern "C" void kernel_launch(void* const* d_in, const int* in_sizes, int n_in,
                              void* d_out, int out_size)
{
    (void)in_sizes; (void)n_in; (void)out_size;

    const float* x = (const float*)d_in[0];
    const float* in_w[2]   = { (const float*)d_in[1],  (const float*)d_in[10] };
    const float* conv_w[2] = { (const float*)d_in[2],  (const float*)d_in[11] };
    const float* conv_b[2] = { (const float*)d_in[3],  (const float*)d_in[12] };
    const float* x_w[2]    = { (const float*)d_in[4],  (const float*)d_in[13] };
    const float* dt_w[2]   = { (const float*)d_in[5],  (const float*)d_in[14] };
    const float* dt_b[2]   = { (const float*)d_in[6],  (const float*)d_in[15] };
    const float* A_log[2]  = { (const float*)d_in[7],  (const float*)d_in[16] };
    const float* Dp[2]     = { (const float*)d_in[8],  (const float*)d_in[17] };
    const float* out_w[2]  = { (const float*)d_in[9],  (const float*)d_in[18] };
    const float* ff_ln_g = (const float*)d_in[19];
    const float* ff_ln_b = (const float*)d_in[20];
    const float* ff_w1   = (const float*)d_in[21];
    const float* ff_b1   = (const float*)d_in[22];
    const float* ff_w2   = (const float*)d_in[23];
    const float* ff_b2   = (const float*)d_in[24];

    float *xz, *xc, *xdbl, *dtb, *yb, *ydir, *xsum, *lnb, *ff1;
    cudaGetSymbolAddress((void**)&xz,   g_xz);
    cudaGetSymbolAddress((void**)&xc,   g_xc);
    cudaGetSymbolAddress((void**)&xdbl, g_xdbl);
    cudaGetSymbolAddress((void**)&dtb,  g_dt);
    cudaGetSymbolAddress((void**)&yb,   g_y);
    cudaGetSymbolAddress((void**)&ydir, g_ydir);
    cudaGetSymbolAddress((void**)&xsum, g_xsum);
    cudaGetSymbolAddress((void**)&lnb,  g_ln);
    cudaGetSymbolAddress((void**)&ff1,  g_ff1);

    cudaFuncSetAttribute(mma_gemm, cudaFuncAttributeMaxDynamicSharedMemorySize, DSMEM);

    const size_t szXZ   = (size_t)ML * 2 * DIN;
    const size_t szXC   = (size_t)ML * DIN;
    const size_t szXDBL = (size_t)ML * 96;
    const size_t szYDIR = (size_t)ML * DM;

    dim3 blk(256);

    for (int dir = 0; dir < 2; dir++) {
        float* xz_d   = xz   + dir * szXZ;
        float* xc_d   = xc   + dir * szXC;
        float* xdbl_d = xdbl + dir * szXDBL;
        float* dt_d   = dtb  + dir * szXC;
        float* y_d    = yb   + dir * szXC;
        float* ydir_d = ydir + dir * szYDIR;

        // in-proj: xz = x @ in_w^T (M=4096, N=4096, K=1024), flipA for bwd
        mma_gemm<<<dim3(4096/128, 4096/128), blk, DSMEM>>>(
            x, DM, in_w[dir], DM, nullptr, nullptr,
            xz_d, 2*DIN, DM, 0, dir, 0);

        conv_kernel<<<(ML*DIN + 255)/256, blk>>>(xz_d, conv_w[dir], conv_b[dir], xc_d);

        // xdbl = xc @ x_w^T (N=96, K=2048) — small, fp32
        sgemm_kernel<<<dim3(1, 4096/128), blk>>>(
            xc_d, DIN, x_w[dir], DIN, nullptr, nullptr,
            xdbl_d, 96, ML, 96, DIN, 0, 0, 0);

        // dt = softplus(xdbl[:, :64] @ dt_w^T + dt_b) (N=2048, K=64) — small, fp32
        sgemm_kernel<<<dim3(2048/128, 4096/128), blk>>>(
            xdbl_d, 96, dt_w[dir], RDT, dt_b[dir], nullptr,
            dt_d, DIN, ML, DIN, RDT, 2, 0, 0);

        scan_kernel<<<256, blk>>>(dt_d, xc_d, xdbl_d, xz_d, A_log[dir], Dp[dir], y_d);

        // out-proj: ydir = y @ out_w^T (N=1024, K=2048), flipC for bwd
        mma_gemm<<<dim3(1024/128, 4096/128), blk, DSMEM>>>(
            y_d, DIN, out_w[dir], DIN, nullptr, nullptr,
            ydir_d, DM, DIN, 0, 0, dir);
    }

    residual_kernel<<<(ML*DM/4 + 255)/256, blk>>>(x, ydir, ydir + szYDIR, xsum);
    ln_kernel<<<ML, blk>>>(xsum, ff_ln_g, ff_ln_b, lnb);

    // ff1 = silu(ln @ ff_w1^T + b1)  (M=4096, N=4096, K=1024)
    mma_gemm<<<dim3(4096/128, 4096/128), blk, DSMEM>>>(
        lnb, DM, ff_w1, DM, ff_b1, nullptr,
        ff1, DFF, DM, 1, 0, 0);

    // out = xsum + (ff1 @ ff_w2^T + b2)  (M=4096, N=1024, K=4096)
    mma_gemm<<<dim3(1024/128, 4096/128), blk, DSMEM>>>(
        ff1, DFF, ff_w2, DFF, ff_b2, xsum,
        (float*)d_out, DM, DFF, 0, 0, 0);
}

// round 4
// speedup vs baseline: 2.0501x; 1.6237x over previous
#include <cuda_runtime.h>
#include <cuda_bf16.h>
#include <math.h>
#include <stdint.h>

// Problem constants
#define BB   2
#define LS   2048
#define DM   1024
#define DIN  2048
#define DST  16
#define RDT  64
#define ML   (BB*LS)      // 4096 rows
#define DFF  (4*DM)       // 4096

typedef __nv_bfloat16 bf16;

// ---------------- scratch (device globals) -----------------------------------
__device__ __align__(256) float g_xz  [2u * ML * 2 * DIN];
__device__ __align__(256) float g_xc  [2u * ML * DIN];
__device__ __align__(256) float g_xdbl[2u * ML * 96];
__device__ __align__(256) float g_dt  [2u * ML * DIN];
__device__ __align__(256) float g_ydir[2u * ML * DM];
__device__ __align__(256) float g_xsum[(size_t)ML * DM];

__device__ __align__(256) bf16 g_xhi [(size_t)ML * DM],  g_xlo [(size_t)ML * DM];
__device__ __align__(256) bf16 g_yhi [2u * ML * DIN],    g_ylo [2u * ML * DIN];
__device__ __align__(256) bf16 g_lnhi[(size_t)ML * DM],  g_lnlo[(size_t)ML * DM];
__device__ __align__(256) bf16 g_f1hi[(size_t)ML * DFF], g_f1lo[(size_t)ML * DFF];
__device__ __align__(256) bf16 g_inwhi [2u * 2 * DIN * DM], g_inwlo [2u * 2 * DIN * DM];
__device__ __align__(256) bf16 g_outwhi[2u * DM * DIN],     g_outwlo[2u * DM * DIN];
__device__ __align__(256) bf16 g_w1hi[(size_t)DFF * DM],  g_w1lo[(size_t)DFF * DM];
__device__ __align__(256) bf16 g_w2hi[(size_t)DM * DFF],  g_w2lo[(size_t)DM * DFF];

// ---------------- helpers ------------------------------------------------------
__device__ __forceinline__ float siluf(float v) { return v / (1.f + expf(-v)); }
__device__ __forceinline__ float softplusf(float v) { return (v > 20.f) ? v : log1pf(expf(v)); }

__device__ __forceinline__ uint32_t pack2(float a, float b) {
    __nv_bfloat16 x = __float2bfloat16(a), y = __float2bfloat16(b);
    return (uint32_t)__bfloat16_as_ushort(x) | ((uint32_t)__bfloat16_as_ushort(y) << 16);
}
__device__ __forceinline__ void split1(float f, float& hi_f, unsigned short& h, unsigned short& l) {
    __nv_bfloat16 hb = __float2bfloat16(f);
    hi_f = __bfloat162float(hb);
    h = __bfloat16_as_ushort(hb);
    l = __bfloat16_as_ushort(__float2bfloat16(f - hi_f));
}

#define LDSM4(r0, r1, r2, r3, addr) \
    asm volatile("ldmatrix.sync.aligned.m8n8.x4.shared.b16 {%0,%1,%2,%3}, [%4];" \
        : "=r"(r0), "=r"(r1), "=r"(r2), "=r"(r3) : "r"(addr))

#define MMA16816(d, a, b0, b1) \
    asm volatile("mma.sync.aligned.m16n8k16.row.col.f32.bf16.bf16.f32 " \
        "{%0,%1,%2,%3}, {%4,%5,%6,%7}, {%8,%9}, {%0,%1,%2,%3};" \
        : "+f"((d)[0]), "+f"((d)[1]), "+f"((d)[2]), "+f"((d)[3]) \
        : "r"((a)[0]), "r"((a)[1]), "r"((a)[2]), "r"((a)[3]), "r"(b0), "r"(b1))

#define CPA16(sa, ga) \
    asm volatile("cp.async.cg.shared.global [%0], [%1], 16;" :: "r"(sa), "l"(ga))
#define CPA_COMMIT() asm volatile("cp.async.commit_group;" ::: "memory")
#define CPA_WAIT1()  asm volatile("cp.async.wait_group 1;" ::: "memory")

// ---------------- split-bf16 tensor-core GEMM (pre-split inputs) ---------------
// C[M,N] = A[M,K] * B[N,K]^T with A,B given as bf16 hi/lo pairs.
// 128x128 tiles, K-chunk 32, 3-stage cp.async pipeline, 8 warps (2Mx4N).
#define KC       32
#define ARR_B    8192            // one [128][32] bf16 array
#define STAGE_B  (4 * ARR_B)     // Ahi, Alo, Bhi, Blo = 32KB
#define NSTAGE   3
#define DSMEM2   (NSTAGE * STAGE_B)

__global__ __launch_bounds__(256, 2)
void mma_gemm2(const bf16* __restrict__ Ahi, const bf16* __restrict__ Alo, int lda,
               const bf16* __restrict__ Bhi, const bf16* __restrict__ Blo, int ldb,
               const float* __restrict__ bias,
               const float* __restrict__ addsrc,
               float* __restrict__ Cf,
               bf16* __restrict__ Chi, bf16* __restrict__ Clo,
               int ldc, int K, int act, int flipA, int flipC)
{
    extern __shared__ char sm[];
    const int tid  = threadIdx.x;
    const int lane = tid & 31;
    const int wid  = tid >> 5;
    const int wm   = wid >> 2;   // 0..1
    const int wn   = wid & 3;    // 0..3
    const int rowBase = blockIdx.y * 128;
    const int colBase = blockIdx.x * 128;
    const uint32_t smb = (uint32_t)__cvta_generic_to_shared(sm);

    // ---- cp.async staging setup: each thread moves 8x16B per stage ----
    const int crow = tid >> 2;          // 0..63
    const int cck  = tid & 3;           // 16B chunk within 64B row
    int ar0 = rowBase + crow, ar1 = rowBase + crow + 64;
    if (flipA) { ar0 ^= (LS - 1); ar1 ^= (LS - 1); }
    const size_t offA0 = (size_t)ar0 * lda + cck * 8;
    const size_t offA1 = (size_t)ar1 * lda + cck * 8;
    const size_t offB0 = (size_t)(colBase + crow) * ldb + cck * 8;
    const size_t offB1 = (size_t)(colBase + crow + 64) * ldb + cck * 8;
    const uint32_t s0 = (uint32_t)crow * 64        + (uint32_t)((cck ^ ((crow >> 1) & 3)) * 16);
    const uint32_t s1 = (uint32_t)(crow + 64) * 64 + (uint32_t)((cck ^ (((crow + 64) >> 1) & 3)) * 16);

    // ---- ldmatrix addressing ----
    const int laneAr = (lane & 7) + ((lane >> 3) & 1) * 8;
    const int aCk    = (lane >> 4);             // 0..1
    const int laneBr = (lane & 7) + ((lane >> 4) & 1) * 8;
    const int bCk    = (lane >> 3) & 1;
    uint32_t aRowB[4], aSw[4], bRowB[2], bSw[2];
    #pragma unroll
    for (int i = 0; i < 4; i++) {
        int r = wm * 64 + i * 16 + laneAr;
        aRowB[i] = (uint32_t)r * 64;
        aSw[i]   = (uint32_t)((r >> 1) & 3);
    }
    #pragma unroll
    for (int p = 0; p < 2; p++) {
        int r = wn * 32 + p * 16 + laneBr;
        bRowB[p] = (uint32_t)r * 64;
        bSw[p]   = (uint32_t)((r >> 1) & 3);
    }

    float acc[16][4];
    #pragma unroll
    for (int i = 0; i < 16; i++)
        #pragma unroll
        for (int j = 0; j < 4; j++) acc[i][j] = 0.f;

    const int nk = K / KC;

    // issue one stage's copies
    auto issue = [&](int stg, int kt) {
        const uint32_t sb = smb + (uint32_t)stg * STAGE_B;
        const size_t ko = (size_t)kt * KC;
        CPA16(sb + 0*ARR_B + s0, Ahi + offA0 + ko);
        CPA16(sb + 0*ARR_B + s1, Ahi + offA1 + ko);
        CPA16(sb + 1*ARR_B + s0, Alo + offA0 + ko);
        CPA16(sb + 1*ARR_B + s1, Alo + offA1 + ko);
        CPA16(sb + 2*ARR_B + s0, Bhi + offB0 + ko);
        CPA16(sb + 2*ARR_B + s1, Bhi + offB1 + ko);
        CPA16(sb + 3*ARR_B + s0, Blo + offB0 + ko);
        CPA16(sb + 3*ARR_B + s1, Blo + offB1 + ko);
    };

    issue(0, 0); CPA_COMMIT();
    issue(1, 1); CPA_COMMIT();

    int stg = 0;
    for (int kt = 0; kt < nk; kt++) {
        CPA_WAIT1();
        __syncthreads();
        if (kt + 2 < nk) issue((stg + 2) % NSTAGE, kt + 2);
        CPA_COMMIT();

        const uint32_t base = smb + (uint32_t)stg * STAGE_B;
        #pragma unroll
        for (int ks = 0; ks < 2; ks++) {
            uint32_t aH[4][4], aL[4][4], bH[2][4], bL[2][4];
            #pragma unroll
            for (int i = 0; i < 4; i++)
                LDSM4(aH[i][0], aH[i][1], aH[i][2], aH[i][3],
                      base + 0*ARR_B + aRowB[i] + (((uint32_t)(ks*2 + aCk) ^ aSw[i]) * 16));
            #pragma unroll
            for (int p = 0; p < 2; p++)
                LDSM4(bH[p][0], bH[p][1], bH[p][2], bH[p][3],
                      base + 2*ARR_B + bRowB[p] + (((uint32_t)(ks*2 + bCk) ^ bSw[p]) * 16));
            // hi*hi
            #pragma unroll
            for (int i = 0; i < 4; i++)
                #pragma unroll
                for (int nt = 0; nt < 4; nt++)
                    MMA16816(acc[i*4+nt], aH[i], bH[nt>>1][(nt&1)*2], bH[nt>>1][(nt&1)*2+1]);
            // lo*hi
            #pragma unroll
            for (int i = 0; i < 4; i++)
                LDSM4(aL[i][0], aL[i][1], aL[i][2], aL[i][3],
                      base + 1*ARR_B + aRowB[i] + (((uint32_t)(ks*2 + aCk) ^ aSw[i]) * 16));
            #pragma unroll
            for (int i = 0; i < 4; i++)
                #pragma unroll
                for (int nt = 0; nt < 4; nt++)
                    MMA16816(acc[i*4+nt], aL[i], bH[nt>>1][(nt&1)*2], bH[nt>>1][(nt&1)*2+1]);
            // hi*lo
            #pragma unroll
            for (int p = 0; p < 2; p++)
                LDSM4(bL[p][0], bL[p][1], bL[p][2], bL[p][3],
                      base + 3*ARR_B + bRowB[p] + (((uint32_t)(ks*2 + bCk) ^ bSw[p]) * 16));
            #pragma unroll
            for (int i = 0; i < 4; i++)
                #pragma unroll
                for (int nt = 0; nt < 4; nt++)
                    MMA16816(acc[i*4+nt], aH[i], bL[nt>>1][(nt&1)*2], bL[nt>>1][(nt&1)*2+1]);
        }
        stg = (stg + 1) % NSTAGE;
    }

    // ---- epilogue from registers ----
    const int erow  = wm * 64 + (lane >> 2);
    const int ecol0 = wn * 32 + (lane & 3) * 2;
    #pragma unroll
    for (int i = 0; i < 4; i++) {
        int r0 = rowBase + erow + i * 16;
        int r1 = r0 + 8;
        int rw0 = flipC ? (r0 ^ (LS - 1)) : r0;
        int rw1 = flipC ? (r1 ^ (LS - 1)) : r1;
        #pragma unroll
        for (int nt = 0; nt < 4; nt++) {
            int c = colBase + ecol0 + nt * 8;
            float v0 = acc[i*4+nt][0], v1 = acc[i*4+nt][1];
            float v2 = acc[i*4+nt][2], v3 = acc[i*4+nt][3];
            if (bias) {
                float b0 = __ldg(&bias[c]), b1 = __ldg(&bias[c+1]);
                v0 += b0; v1 += b1; v2 += b0; v3 += b1;
            }
            if (act == 1) { v0 = siluf(v0); v1 = siluf(v1); v2 = siluf(v2); v3 = siluf(v3); }
            else if (act == 2) { v0 = softplusf(v0); v1 = softplusf(v1); v2 = softplusf(v2); v3 = softplusf(v3); }
            if (addsrc) {
                v0 += addsrc[(size_t)rw0 * ldc + c];
                v1 += addsrc[(size_t)rw0 * ldc + c + 1];
                v2 += addsrc[(size_t)rw1 * ldc + c];
                v3 += addsrc[(size_t)rw1 * ldc + c + 1];
            }
            if (Cf) {
                *(float2*)&Cf[(size_t)rw0 * ldc + c] = make_float2(v0, v1);
                *(float2*)&Cf[(size_t)rw1 * ldc + c] = make_float2(v2, v3);
            } else {
                float h0f, h1f, h2f, h3f;
                unsigned short h0,h1,h2,h3,l0,l1,l2,l3;
                split1(v0, h0f, h0, l0); split1(v1, h1f, h1, l1);
                split1(v2, h2f, h2, l2); split1(v3, h3f, h3, l3);
                *(uint32_t*)(Chi + (size_t)rw0 * ldc + c) = (uint32_t)h0 | ((uint32_t)h1 << 16);
                *(uint32_t*)(Clo + (size_t)rw0 * ldc + c) = (uint32_t)l0 | ((uint32_t)l1 << 16);
                *(uint32_t*)(Chi + (size_t)rw1 * ldc + c) = (uint32_t)h2 | ((uint32_t)h3 << 16);
                *(uint32_t*)(Clo + (size_t)rw1 * ldc + c) = (uint32_t)l2 | ((uint32_t)l3 << 16);
            }
        }
    }
}

// ---------------- fp32 -> bf16 hi/lo split --------------------------------------
__global__ void split_kernel(const float* __restrict__ in,
                             bf16* __restrict__ hi,
                             bf16* __restrict__ lo, int n4)
{
    int i = blockIdx.x * blockDim.x + threadIdx.x;
    if (i >= n4) return;
    float4 v = ((const float4*)in)[i];
    float hf; unsigned short h0,h1,h2,h3,l0,l1,l2,l3;
    split1(v.x, hf, h0, l0); split1(v.y, hf, h1, l1);
    split1(v.z, hf, h2, l2); split1(v.w, hf, h3, l3);
    uint2 hu, lu;
    hu.x = (uint32_t)h0 | ((uint32_t)h1 << 16);
    hu.y = (uint32_t)h2 | ((uint32_t)h3 << 16);
    lu.x = (uint32_t)l0 | ((uint32_t)l1 << 16);
    lu.y = (uint32_t)l2 | ((uint32_t)l3 << 16);
    *(uint2*)(hi + (size_t)i * 4) = hu;
    *(uint2*)(lo + (size_t)i * 4) = lu;
}

// ---------------- fp32 SGEMM (small GEMMs: xdbl, dt) ----------------------------
__global__ __launch_bounds__(256)
void sgemm_kernel(const float* __restrict__ A, int lda,
                  const float* __restrict__ Bw, int ldb,
                  const float* __restrict__ bias,
                  float* __restrict__ C, int ldc,
                  int M, int N, int K, int act)
{
    __shared__ float As[16][132];
    __shared__ float Bs[16][132];

    const int tid = threadIdx.x;
    const int tx = tid & 15;
    const int ty = tid >> 4;
    const int rowBase = blockIdx.y * 128;
    const int colBase = blockIdx.x * 128;

    const int lm = tid >> 1;
    const int lk = (tid & 1) * 8;

    const float* aPtr = A + (size_t)(rowBase + lm) * lda + lk;
    const int bRow = colBase + lm;
    const bool bValid = bRow < N;
    const float* bPtr = Bw + (size_t)bRow * ldb + lk;

    float acc[8][8];
    #pragma unroll
    for (int i = 0; i < 8; i++)
        #pragma unroll
        for (int j = 0; j < 8; j++) acc[i][j] = 0.f;

    for (int k0 = 0; k0 < K; k0 += 16) {
        float4 a0 = *(const float4*)(aPtr + k0);
        float4 a1 = *(const float4*)(aPtr + k0 + 4);
        float4 b0 = bValid ? *(const float4*)(bPtr + k0)     : make_float4(0,0,0,0);
        float4 b1 = bValid ? *(const float4*)(bPtr + k0 + 4) : make_float4(0,0,0,0);

        As[lk+0][lm] = a0.x; As[lk+1][lm] = a0.y; As[lk+2][lm] = a0.z; As[lk+3][lm] = a0.w;
        As[lk+4][lm] = a1.x; As[lk+5][lm] = a1.y; As[lk+6][lm] = a1.z; As[lk+7][lm] = a1.w;
        Bs[lk+0][lm] = b0.x; Bs[lk+1][lm] = b0.y; Bs[lk+2][lm] = b0.z; Bs[lk+3][lm] = b0.w;
        Bs[lk+4][lm] = b1.x; Bs[lk+5][lm] = b1.y; Bs[lk+6][lm] = b1.z; Bs[lk+7][lm] = b1.w;
        __syncthreads();

        #pragma unroll
        for (int kk = 0; kk < 16; kk++) {
            float4 ra0 = *(const float4*)&As[kk][ty * 4];
            float4 ra1 = *(const float4*)&As[kk][64 + ty * 4];
            float4 rb0 = *(const float4*)&Bs[kk][tx * 4];
            float4 rb1 = *(const float4*)&Bs[kk][64 + tx * 4];
            float ar[8] = {ra0.x, ra0.y, ra0.z, ra0.w, ra1.x, ra1.y, ra1.z, ra1.w};
            float br[8] = {rb0.x, rb0.y, rb0.z, rb0.w, rb1.x, rb1.y, rb1.z, rb1.w};
            #pragma unroll
            for (int i = 0; i < 8; i++)
                #pragma unroll
                for (int j = 0; j < 8; j++)
                    acc[i][j] = fmaf(ar[i], br[j], acc[i][j]);
        }
        __syncthreads();
    }

    #pragma unroll
    for (int i = 0; i < 8; i++) {
        int r = rowBase + ((i < 4) ? (ty * 4 + i) : (64 + ty * 4 + i - 4));
        #pragma unroll
        for (int j = 0; j < 8; j++) {
            int c = colBase + ((j < 4) ? (tx * 4 + j) : (64 + tx * 4 + j - 4));
            if (c < N) {
                float v = acc[i][j];
                if (bias) v += bias[c];
                if (act == 2) v = softplusf(v);
                C[(size_t)r * ldc + c] = v;
            }
        }
    }
}

// ---------------- depthwise causal conv (k=4) + bias + silu ---------------------
__global__ void conv_kernel(const float* __restrict__ xz,
                            const float* __restrict__ cw,
                            const float* __restrict__ cb,
                            float* __restrict__ xc)
{
    int idx = blockIdx.x * blockDim.x + threadIdx.x;
    if (idx >= ML * DIN) return;
    int c = idx & (DIN - 1);
    int r = idx / DIN;
    int l = r & (LS - 1);
    int b = r / LS;
    float acc = cb[c];
    float w0 = cw[c * 4 + 0], w1 = cw[c * 4 + 1], w2 = cw[c * 4 + 2], w3 = cw[c * 4 + 3];
    #pragma unroll
    for (int k = 0; k < 4; k++) {
        int lp = l - 3 + k;
        if (lp >= 0) {
            float w = (k == 0) ? w0 : (k == 1) ? w1 : (k == 2) ? w2 : w3;
            acc += xz[((size_t)(b * LS + lp)) * (2 * DIN) + c] * w;
        }
    }
    xc[idx] = siluf(acc);
}

// ---------------- selective scan (pipelined loads, bf16 hi/lo out) --------------
__global__ void scan_kernel(const float* __restrict__ dt,
                            const float* __restrict__ xc,
                            const float* __restrict__ xdbl,
                            const float* __restrict__ xz,
                            const float* __restrict__ A_log,
                            const float* __restrict__ Dp,
                            bf16* __restrict__ yhi,
                            bf16* __restrict__ ylo)
{
    int gwarp = (blockIdx.x * blockDim.x + threadIdx.x) >> 5;
    int lane = threadIdx.x & 31;
    int half = lane >> 4;
    int s = lane & 15;
    int row = gwarp * 2 + half;
    if (row >= BB * DIN) return;
    int b = row / DIN;
    int d = row % DIN;

    float Av = -expf(A_log[d * DST + s]);
    float Dd = Dp[d];
    float h = 0.f;
    const bool w0lane = (s == 0);

    size_t base = (size_t)b * LS;
    // prefetch l=0
    float dtv = dt[base * DIN + d];
    float uv  = xc[base * DIN + d];
    float Bv  = xdbl[base * 96 + RDT + s];
    float Cv  = xdbl[base * 96 + RDT + DST + s];
    float zv  = w0lane ? xz[base * (2 * DIN) + DIN + d] : 0.f;

    for (int l = 0; l < LS; l++) {
        size_t nb = base + ((l + 1 < LS) ? (l + 1) : l);
        float dtn = dt[nb * DIN + d];
        float un  = xc[nb * DIN + d];
        float Bn  = xdbl[nb * 96 + RDT + s];
        float Cn  = xdbl[nb * 96 + RDT + DST + s];
        float zn  = w0lane ? xz[nb * (2 * DIN) + DIN + d] : 0.f;

        h = h * expf(dtv * Av) + dtv * uv * Bv;
        float y = h * Cv;
        y += __shfl_xor_sync(0xffffffffu, y, 8);
        y += __shfl_xor_sync(0xffffffffu, y, 4);
        y += __shfl_xor_sync(0xffffffffu, y, 2);
        y += __shfl_xor_sync(0xffffffffu, y, 1);
        if (w0lane) {
            float yv = (y + uv * Dd) * siluf(zv);
            __nv_bfloat16 hb = __float2bfloat16(yv);
            size_t o = (base + l) * DIN + d;
            yhi[o] = hb;
            ylo[o] = __float2bfloat16(yv - __bfloat162float(hb));
        }
        dtv = dtn; uv = un; Bv = Bn; Cv = Cn; zv = zn;
    }
}

// ---------------- residual combine ------------------------------------------------
__global__ void residual_kernel(const float* __restrict__ x,
                                const float* __restrict__ y0,
                                const float* __restrict__ y1,
                                float* __restrict__ xsum)
{
    int i = blockIdx.x * blockDim.x + threadIdx.x;
    int n = ML * DM / 4;
    if (i >= n) return;
    float4 xv = ((const float4*)x)[i];
    float4 a = ((const float4*)y0)[i];
    float4 b = ((const float4*)y1)[i];
    float4 o;
    o.x = xv.x + 0.5f * (a.x + b.x);
    o.y = xv.y + 0.5f * (a.y + b.y);
    o.z = xv.z + 0.5f * (a.z + b.z);
    o.w = xv.w + 0.5f * (a.w + b.w);
    ((float4*)xsum)[i] = o;
}

// ---------------- layernorm (1024) -> bf16 hi/lo -----------------------------------
__global__ void ln_kernel(const float* __restrict__ xin,
                          const float* __restrict__ g,
                          const float* __restrict__ bta,
                          bf16* __restrict__ outhi,
                          bf16* __restrict__ outlo)
{
    int row = blockIdx.x;
    const float4* xr = (const float4*)(xin + (size_t)row * DM);
    float4 v = xr[threadIdx.x];
    float s  = v.x + v.y + v.z + v.w;
    float sq = v.x*v.x + v.y*v.y + v.z*v.z + v.w*v.w;

    #pragma unroll
    for (int o = 16; o >= 1; o >>= 1) {
        s  += __shfl_xor_sync(0xffffffffu, s, o);
        sq += __shfl_xor_sync(0xffffffffu, sq, o);
    }
    __shared__ float ss[8], ssq[8];
    int warp = threadIdx.x >> 5, lane = threadIdx.x & 31;
    if (lane == 0) { ss[warp] = s; ssq[warp] = sq; }
    __syncthreads();
    __shared__ float sh_mean, sh_inv;
    if (threadIdx.x == 0) {
        float ts = 0.f, tq = 0.f;
        #pragma unroll
        for (int w = 0; w < 8; w++) { ts += ss[w]; tq += ssq[w]; }
        float mean = ts / DM;
        float var = tq / DM - mean * mean;
        sh_mean = mean;
        sh_inv = rsqrtf(var + 1e-5f);
    }
    __syncthreads();
    float mean = sh_mean, inv = sh_inv;
    float4 gv = ((const float4*)g)[threadIdx.x];
    float4 bv = ((const float4*)bta)[threadIdx.x];
    float o0 = (v.x - mean) * inv * gv.x + bv.x;
    float o1 = (v.y - mean) * inv * gv.y + bv.y;
    float o2 = (v.z - mean) * inv * gv.z + bv.z;
    float o3 = (v.w - mean) * inv * gv.w + bv.w;
    float hf; unsigned short h0,h1,h2,h3,l0,l1,l2,l3;
    split1(o0, hf, h0, l0); split1(o1, hf, h1, l1);
    split1(o2, hf, h2, l2); split1(o3, hf, h3, l3);
    uint2 hu, lu;
    hu.x = (uint32_t)h0 | ((uint32_t)h1 << 16);
    hu.y = (uint32_t)h2 | ((uint32_t)h3 << 16);
    lu.x = (uint32_t)l0 | ((uint32_t)l1 << 16);
    lu.y = (uint32_t)l2 | ((uint32_t)l3 << 16);
    size_t off = (size_t)row * DM + threadIdx.x * 4;
    *(uint2*)(outhi + off) = hu;
    *(uint2*)(outlo + off) = lu;
}

// ---------------- host orchestration ------------------------------------------------
extern "C" void kernel_launch(void* const* d_in, const int* in_sizes, int n_in,
                              void* d_out, int out_size)
{
    (void)in_sizes; (void)n_in; (void)out_size;

    const float* x = (const float*)d_in[0];
    const float* in_w[2]   = { (const float*)d_in[1],  (const float*)d_in[10] };
    const float* conv_w[2] = { (const float*)d_in[2],  (const float*)d_in[11] };
    const float* conv_b[2] = { (const float*)d_in[3],  (const float*)d_in[12] };
    const float* x_w[2]    = { (const float*)d_in[4],  (const float*)d_in[13] };
    const float* dt_w[2]   = { (const float*)d_in[5],  (const float*)d_in[14] };
    const float* dt_b[2]   = { (const float*)d_in[6],  (const float*)d_in[15] };
    const float* A_log[2]  = { (const float*)d_in[7],  (const float*)d_in[16] };
    const float* Dp[2]     = { (const float*)d_in[8],  (const float*)d_in[17] };
    const float* out_w[2]  = { (const float*)d_in[9],  (const float*)d_in[18] };
    const float* ff_ln_g = (const float*)d_in[19];
    const float* ff_ln_b = (const float*)d_in[20];
    const float* ff_w1   = (const float*)d_in[21];
    const float* ff_b1   = (const float*)d_in[22];
    const float* ff_w2   = (const float*)d_in[23];
    const float* ff_b2   = (const float*)d_in[24];

    float *xz, *xc, *xdbl, *dtb, *ydir, *xsum;
    bf16 *xhi, *xlo, *yhi, *ylo, *lnhi, *lnlo, *f1hi, *f1lo;
    bf16 *inwhi, *inwlo, *outwhi, *outwlo, *w1hi, *w1lo, *w2hi, *w2lo;
    cudaGetSymbolAddress((void**)&xz,   g_xz);
    cudaGetSymbolAddress((void**)&xc,   g_xc);
    cudaGetSymbolAddress((void**)&xdbl, g_xdbl);
    cudaGetSymbolAddress((void**)&dtb,  g_dt);
    cudaGetSymbolAddress((void**)&ydir, g_ydir);
    cudaGetSymbolAddress((void**)&xsum, g_xsum);
    cudaGetSymbolAddress((void**)&xhi,  g_xhi);
    cudaGetSymbolAddress((void**)&xlo,  g_xlo);
    cudaGetSymbolAddress((void**)&yhi,  g_yhi);
    cudaGetSymbolAddress((void**)&ylo,  g_ylo);
    cudaGetSymbolAddress((void**)&lnhi, g_lnhi);
    cudaGetSymbolAddress((void**)&lnlo, g_lnlo);
    cudaGetSymbolAddress((void**)&f1hi, g_f1hi);
    cudaGetSymbolAddress((void**)&f1lo, g_f1lo);
    cudaGetSymbolAddress((void**)&inwhi,  g_inwhi);
    cudaGetSymbolAddress((void**)&inwlo,  g_inwlo);
    cudaGetSymbolAddress((void**)&outwhi, g_outwhi);
    cudaGetSymbolAddress((void**)&outwlo, g_outwlo);
    cudaGetSymbolAddress((void**)&w1hi, g_w1hi);
    cudaGetSymbolAddress((void**)&w1lo, g_w1lo);
    cudaGetSymbolAddress((void**)&w2hi, g_w2hi);
    cudaGetSymbolAddress((void**)&w2lo, g_w2lo);

    cudaFuncSetAttribute(mma_gemm2, cudaFuncAttributeMaxDynamicSharedMemorySize, DSMEM2);

    const size_t szXZ   = (size_t)ML * 2 * DIN;
    const size_t szXC   = (size_t)ML * DIN;
    const size_t szXDBL = (size_t)ML * 96;
    const size_t szYDIR = (size_t)ML * DM;
    const size_t szINW  = (size_t)2 * DIN * DM;
    const size_t szOUTW = (size_t)DM * DIN;

    dim3 blk(256);

    // 5 split launches first (slots 0-4), so the 6th launch (ncu -s 5 -c 1) is in-proj mma
    split_kernel<<<(ML*DM/4 + 255)/256, blk>>>(x, xhi, xlo, ML*DM/4);
    split_kernel<<<((int)szINW/4 + 255)/256, blk>>>(in_w[0],  inwhi,          inwlo,          (int)szINW/4);
    split_kernel<<<((int)szINW/4 + 255)/256, blk>>>(in_w[1],  inwhi + szINW,  inwlo + szINW,  (int)szINW/4);
    split_kernel<<<((int)szOUTW/4 + 255)/256, blk>>>(out_w[0], outwhi,          outwlo,          (int)szOUTW/4);
    split_kernel<<<((int)szOUTW/4 + 255)/256, blk>>>(out_w[1], outwhi + szOUTW, outwlo + szOUTW, (int)szOUTW/4);

    for (int dir = 0; dir < 2; dir++) {
        float* xz_d   = xz   + dir * szXZ;
        float* xc_d   = xc   + dir * szXC;
        float* xdbl_d = xdbl + dir * szXDBL;
        float* dt_d   = dtb  + dir * szXC;
        float* ydir_d = ydir + dir * szYDIR;
        bf16* yhi_d = yhi + dir * szXC;
        bf16* ylo_d = ylo + dir * szXC;

        // in-proj: xz = x @ in_w^T (M=4096, N=4096, K=1024), flipA for bwd
        mma_gemm2<<<dim3(32, 32), blk, DSMEM2>>>(
            xhi, xlo, DM, inwhi + dir*szINW, inwlo + dir*szINW, DM,
            nullptr, nullptr, xz_d, nullptr, nullptr,
            2*DIN, DM, 0, dir, 0);

        conv_kernel<<<(ML*DIN + 255)/256, blk>>>(xz_d, conv_w[dir], conv_b[dir], xc_d);

        // xdbl = xc @ x_w^T (N=96, K=2048) — small, fp32
        sgemm_kernel<<<dim3(1, 32), blk>>>(
            xc_d, DIN, x_w[dir], DIN, nullptr,
            xdbl_d, 96, ML, 96, DIN, 0);

        // dt = softplus(xdbl[:, :64] @ dt_w^T + dt_b) (N=2048, K=64)
        sgemm_kernel<<<dim3(16, 32), blk>>>(
            xdbl_d, 96, dt_w[dir], RDT, dt_b[dir],
            dt_d, DIN, ML, DIN, RDT, 2);

        scan_kernel<<<256, blk>>>(dt_d, xc_d, xdbl_d, xz_d, A_log[dir], Dp[dir], yhi_d, ylo_d);

        // out-proj: ydir = y @ out_w^T (N=1024, K=2048), flipC for bwd
        mma_gemm2<<<dim3(8, 32), blk, DSMEM2>>>(
            yhi_d, ylo_d, DIN, outwhi + dir*szOUTW, outwlo + dir*szOUTW, DIN,
            nullptr, nullptr, ydir_d, nullptr, nullptr,
            DM, DIN, 0, 0, dir);
    }

    residual_kernel<<<(ML*DM/4 + 255)/256, blk>>>(x, ydir, ydir + szYDIR, xsum);
    ln_kernel<<<ML, blk>>>(xsum, ff_ln_g, ff_ln_b, lnhi, lnlo);

    split_kernel<<<(DFF*DM/4 + 255)/256, blk>>>(ff_w1, w1hi, w1lo, DFF*DM/4);
    split_kernel<<<(DM*DFF/4 + 255)/256, blk>>>(ff_w2, w2hi, w2lo, DM*DFF/4);

    // ff1 = silu(ln @ ff_w1^T + b1) -> bf16 hi/lo (M=4096, N=4096, K=1024)
    mma_gemm2<<<dim3(32, 32), blk, DSMEM2>>>(
        lnhi, lnlo, DM, w1hi, w1lo, DM,
        ff_b1, nullptr, nullptr, f1hi, f1lo,
        DFF, DM, 1, 0, 0);

    // out = xsum + (ff1 @ ff_w2^T + b2) (M=4096, N=1024, K=4096)
    mma_gemm2<<<dim3(8, 32), blk, DSMEM2>>>(
        f1hi, f1lo, DFF, w2hi, w2lo, DFF,
        ff_b2, xsum, (float*)d_out, nullptr, nullptr,
        DM, DFF, 0, 0, 0);
}

// round 5
// speedup vs baseline: 3.0775x; 1.5011x over previous
#include <cuda_runtime.h>
#include <cuda_bf16.h>
#include <math.h>
#include <stdint.h>

// Problem constants
#define BB   2
#define LS   2048
#define DM   1024
#define DIN  2048
#define DST  16
#define RDT  64
#define ML   (BB*LS)      // 4096 rows
#define DFF  (4*DM)       // 4096

typedef __nv_bfloat16 bf16;

// ---------------- scratch (device globals) -----------------------------------
// xz unified: [ML][8192], cols [dir*4096 .. dir*4096+2047]=xi, [+2048..+4095]=z
__device__ __align__(256) float g_xz  [(size_t)ML * 8192];
__device__ __align__(256) float g_xc  [2u * ML * DIN];
__device__ __align__(256) float g_xdbl[2u * ML * 96];
__device__ __align__(256) float g_dt  [2u * ML * DIN];
__device__ __align__(256) float g_ydir[2u * ML * DM];
__device__ __align__(256) float g_xsum[(size_t)ML * DM];

__device__ __align__(256) bf16 g_xhi [(size_t)ML * DM],  g_xlo [(size_t)ML * DM];
__device__ __align__(256) bf16 g_yhi [2u * ML * DIN],    g_ylo [2u * ML * DIN];
__device__ __align__(256) bf16 g_lnhi[(size_t)ML * DM],  g_lnlo[(size_t)ML * DM];
__device__ __align__(256) bf16 g_f1hi[(size_t)ML * DFF], g_f1lo[(size_t)ML * DFF];
__device__ __align__(256) bf16 g_inwhi [2u * 2 * DIN * DM], g_inwlo [2u * 2 * DIN * DM];
__device__ __align__(256) bf16 g_outwhi[2u * DM * DIN],     g_outwlo[2u * DM * DIN];
__device__ __align__(256) bf16 g_w1hi[(size_t)DFF * DM],  g_w1lo[(size_t)DFF * DM];
__device__ __align__(256) bf16 g_w2hi[(size_t)DM * DFF],  g_w2lo[(size_t)DM * DFF];

// ---------------- helpers ------------------------------------------------------
__device__ __forceinline__ float siluf(float v) { return v / (1.f + __expf(-v)); }
__device__ __forceinline__ float softplusf(float v) {
    return (v > 20.f) ? v : log1pf(__expf(v));
}
__device__ __forceinline__ void split1(float f, unsigned short& h, unsigned short& l) {
    __nv_bfloat16 hb = __float2bfloat16(f);
    h = __bfloat16_as_ushort(hb);
    l = __bfloat16_as_ushort(__float2bfloat16(f - __bfloat162float(hb)));
}

#define LDSM4(r0, r1, r2, r3, addr) \
    asm volatile("ldmatrix.sync.aligned.m8n8.x4.shared.b16 {%0,%1,%2,%3}, [%4];" \
        : "=r"(r0), "=r"(r1), "=r"(r2), "=r"(r3) : "r"(addr))

#define MMA16816(d, a, b0, b1) \
    asm volatile("mma.sync.aligned.m16n8k16.row.col.f32.bf16.bf16.f32 " \
        "{%0,%1,%2,%3}, {%4,%5,%6,%7}, {%8,%9}, {%0,%1,%2,%3};" \
        : "+f"((d)[0]), "+f"((d)[1]), "+f"((d)[2]), "+f"((d)[3]) \
        : "r"((a)[0]), "r"((a)[1]), "r"((a)[2]), "r"((a)[3]), "r"(b0), "r"(b1))

#define CPA16(sa, ga) \
    asm volatile("cp.async.cg.shared.global [%0], [%1], 16;" :: "r"(sa), "l"(ga))
#define CPA_COMMIT() asm volatile("cp.async.commit_group;" ::: "memory")
#define CPA_WAIT1()  asm volatile("cp.async.wait_group 1;" ::: "memory")

// ---------------- split-bf16 tensor-core GEMM (pre-split inputs) ---------------
// C[M,N] = A[M,K] * B[N,K]^T, A/B bf16 hi/lo. 128x128 tiles, KC=32, 3-stage.
// blockIdx.z batching via element strides zsA/zsB/zsC.
#define KC       32
#define ARR_B    8192
#define STAGE_B  (4 * ARR_B)
#define NSTAGE   3
#define DSMEM2   (NSTAGE * STAGE_B)

__global__ __launch_bounds__(256, 2)
void mma_gemm2(const bf16* __restrict__ Ahi, const bf16* __restrict__ Alo, int lda,
               const bf16* __restrict__ Bhi, const bf16* __restrict__ Blo, int ldb,
               const float* __restrict__ bias,
               const float* __restrict__ addsrc,
               float* __restrict__ Cf,
               bf16* __restrict__ Chi, bf16* __restrict__ Clo,
               int ldc, int K, int act,
               size_t zsA, size_t zsB, size_t zsC)
{
    extern __shared__ char sm[];
    const int tid  = threadIdx.x;
    const int lane = tid & 31;
    const int wid  = tid >> 5;
    const int wm   = wid >> 2;
    const int wn   = wid & 3;
    const int rowBase = blockIdx.y * 128;
    const int colBase = blockIdx.x * 128;
    const size_t zA = (size_t)blockIdx.z * zsA;
    const size_t zB = (size_t)blockIdx.z * zsB;
    const size_t zC = (size_t)blockIdx.z * zsC;
    const uint32_t smb = (uint32_t)__cvta_generic_to_shared(sm);

    const int crow = tid >> 2;
    const int cck  = tid & 3;
    const size_t offA0 = zA + (size_t)(rowBase + crow) * lda + cck * 8;
    const size_t offA1 = zA + (size_t)(rowBase + crow + 64) * lda + cck * 8;
    const size_t offB0 = zB + (size_t)(colBase + crow) * ldb + cck * 8;
    const size_t offB1 = zB + (size_t)(colBase + crow + 64) * ldb + cck * 8;
    const uint32_t s0 = (uint32_t)crow * 64        + (uint32_t)((cck ^ ((crow >> 1) & 3)) * 16);
    const uint32_t s1 = (uint32_t)(crow + 64) * 64 + (uint32_t)((cck ^ (((crow + 64) >> 1) & 3)) * 16);

    const int laneAr = (lane & 7) + ((lane >> 3) & 1) * 8;
    const int aCk    = (lane >> 4);
    const int laneBr = (lane & 7) + ((lane >> 4) & 1) * 8;
    const int bCk    = (lane >> 3) & 1;
    uint32_t aRowB[4], aSw[4], bRowB[2], bSw[2];
    #pragma unroll
    for (int i = 0; i < 4; i++) {
        int r = wm * 64 + i * 16 + laneAr;
        aRowB[i] = (uint32_t)r * 64;
        aSw[i]   = (uint32_t)((r >> 1) & 3);
    }
    #pragma unroll
    for (int p = 0; p < 2; p++) {
        int r = wn * 32 + p * 16 + laneBr;
        bRowB[p] = (uint32_t)r * 64;
        bSw[p]   = (uint32_t)((r >> 1) & 3);
    }

    float acc[16][4];
    #pragma unroll
    for (int i = 0; i < 16; i++)
        #pragma unroll
        for (int j = 0; j < 4; j++) acc[i][j] = 0.f;

    const int nk = K / KC;

    auto issue = [&](int stg, int kt) {
        const uint32_t sb = smb + (uint32_t)stg * STAGE_B;
        const size_t ko = (size_t)kt * KC;
        CPA16(sb + 0*ARR_B + s0, Ahi + offA0 + ko);
        CPA16(sb + 0*ARR_B + s1, Ahi + offA1 + ko);
        CPA16(sb + 1*ARR_B + s0, Alo + offA0 + ko);
        CPA16(sb + 1*ARR_B + s1, Alo + offA1 + ko);
        CPA16(sb + 2*ARR_B + s0, Bhi + offB0 + ko);
        CPA16(sb + 2*ARR_B + s1, Bhi + offB1 + ko);
        CPA16(sb + 3*ARR_B + s0, Blo + offB0 + ko);
        CPA16(sb + 3*ARR_B + s1, Blo + offB1 + ko);
    };

    issue(0, 0); CPA_COMMIT();
    issue(1, 1); CPA_COMMIT();

    int stg = 0;
    for (int kt = 0; kt < nk; kt++) {
        CPA_WAIT1();
        __syncthreads();
        if (kt + 2 < nk) issue((stg + 2) % NSTAGE, kt + 2);
        CPA_COMMIT();

        const uint32_t base = smb + (uint32_t)stg * STAGE_B;
        #pragma unroll
        for (int ks = 0; ks < 2; ks++) {
            uint32_t aH[4][4], aL[4][4], bH[2][4], bL[2][4];
            #pragma unroll
            for (int i = 0; i < 4; i++)
                LDSM4(aH[i][0], aH[i][1], aH[i][2], aH[i][3],
                      base + 0*ARR_B + aRowB[i] + (((uint32_t)(ks*2 + aCk) ^ aSw[i]) * 16));
            #pragma unroll
            for (int p = 0; p < 2; p++)
                LDSM4(bH[p][0], bH[p][1], bH[p][2], bH[p][3],
                      base + 2*ARR_B + bRowB[p] + (((uint32_t)(ks*2 + bCk) ^ bSw[p]) * 16));
            #pragma unroll
            for (int i = 0; i < 4; i++)
                #pragma unroll
                for (int nt = 0; nt < 4; nt++)
                    MMA16816(acc[i*4+nt], aH[i], bH[nt>>1][(nt&1)*2], bH[nt>>1][(nt&1)*2+1]);
            #pragma unroll
            for (int i = 0; i < 4; i++)
                LDSM4(aL[i][0], aL[i][1], aL[i][2], aL[i][3],
                      base + 1*ARR_B + aRowB[i] + (((uint32_t)(ks*2 + aCk) ^ aSw[i]) * 16));
            #pragma unroll
            for (int i = 0; i < 4; i++)
                #pragma unroll
                for (int nt = 0; nt < 4; nt++)
                    MMA16816(acc[i*4+nt], aL[i], bH[nt>>1][(nt&1)*2], bH[nt>>1][(nt&1)*2+1]);
            #pragma unroll
            for (int p = 0; p < 2; p++)
                LDSM4(bL[p][0], bL[p][1], bL[p][2], bL[p][3],
                      base + 3*ARR_B + bRowB[p] + (((uint32_t)(ks*2 + bCk) ^ bSw[p]) * 16));
            #pragma unroll
            for (int i = 0; i < 4; i++)
                #pragma unroll
                for (int nt = 0; nt < 4; nt++)
                    MMA16816(acc[i*4+nt], aH[i], bL[nt>>1][(nt&1)*2], bL[nt>>1][(nt&1)*2+1]);
        }
        stg = (stg + 1) % NSTAGE;
    }

    const int erow  = wm * 64 + (lane >> 2);
    const int ecol0 = wn * 32 + (lane & 3) * 2;
    #pragma unroll
    for (int i = 0; i < 4; i++) {
        int r0 = rowBase + erow + i * 16;
        int r1 = r0 + 8;
        #pragma unroll
        for (int nt = 0; nt < 4; nt++) {
            int c = colBase + ecol0 + nt * 8;
            float v0 = acc[i*4+nt][0], v1 = acc[i*4+nt][1];
            float v2 = acc[i*4+nt][2], v3 = acc[i*4+nt][3];
            if (bias) {
                float b0 = __ldg(&bias[c]), b1 = __ldg(&bias[c+1]);
                v0 += b0; v1 += b1; v2 += b0; v3 += b1;
            }
            if (act == 1) { v0 = siluf(v0); v1 = siluf(v1); v2 = siluf(v2); v3 = siluf(v3); }
            else if (act == 2) { v0 = softplusf(v0); v1 = softplusf(v1); v2 = softplusf(v2); v3 = softplusf(v3); }
            if (addsrc) {
                v0 += addsrc[(size_t)r0 * ldc + c];
                v1 += addsrc[(size_t)r0 * ldc + c + 1];
                v2 += addsrc[(size_t)r1 * ldc + c];
                v3 += addsrc[(size_t)r1 * ldc + c + 1];
            }
            if (Cf) {
                *(float2*)&Cf[zC + (size_t)r0 * ldc + c] = make_float2(v0, v1);
                *(float2*)&Cf[zC + (size_t)r1 * ldc + c] = make_float2(v2, v3);
            } else {
                unsigned short h0,h1,h2,h3,l0,l1,l2,l3;
                split1(v0, h0, l0); split1(v1, h1, l1);
                split1(v2, h2, l2); split1(v3, h3, l3);
                *(uint32_t*)(Chi + zC + (size_t)r0 * ldc + c) = (uint32_t)h0 | ((uint32_t)h1 << 16);
                *(uint32_t*)(Clo + zC + (size_t)r0 * ldc + c) = (uint32_t)l0 | ((uint32_t)l1 << 16);
                *(uint32_t*)(Chi + zC + (size_t)r1 * ldc + c) = (uint32_t)h2 | ((uint32_t)h3 << 16);
                *(uint32_t*)(Clo + zC + (size_t)r1 * ldc + c) = (uint32_t)l2 | ((uint32_t)l3 << 16);
            }
        }
    }
}

// ---------------- fp32 -> bf16 hi/lo split --------------------------------------
__global__ void split_kernel(const float* __restrict__ in,
                             bf16* __restrict__ hi,
                             bf16* __restrict__ lo, int n4)
{
    int i = blockIdx.x * blockDim.x + threadIdx.x;
    if (i >= n4) return;
    float4 v = ((const float4*)in)[i];
    unsigned short h0,h1,h2,h3,l0,l1,l2,l3;
    split1(v.x, h0, l0); split1(v.y, h1, l1);
    split1(v.z, h2, l2); split1(v.w, h3, l3);
    uint2 hu, lu;
    hu.x = (uint32_t)h0 | ((uint32_t)h1 << 16);
    hu.y = (uint32_t)h2 | ((uint32_t)h3 << 16);
    lu.x = (uint32_t)l0 | ((uint32_t)l1 << 16);
    lu.y = (uint32_t)l2 | ((uint32_t)l3 << 16);
    *(uint2*)(hi + (size_t)i * 4) = hu;
    *(uint2*)(lo + (size_t)i * 4) = lu;
}

// ---------------- xdbl GEMM: [2][ML][96] = xc @ x_w^T, 32-row M-tiles -----------
__global__ __launch_bounds__(128)
void xdbl_gemm(const float* __restrict__ xcA,   // [2][ML][DIN]
               const float* __restrict__ xw0,   // [96][DIN]
               const float* __restrict__ xw1,
               float* __restrict__ out)         // [2][ML][96]
{
    __shared__ float As[16][36];
    __shared__ float Bs[16][100];
    const int dir = blockIdx.z;
    const float* A = xcA + (size_t)dir * ML * DIN + (size_t)blockIdx.x * 32 * DIN;
    const float* B = dir ? xw1 : xw0;
    float* C = out + (size_t)dir * ML * 96 + (size_t)blockIdx.x * 32 * 96;

    const int tid = threadIdx.x;
    const int tx = tid & 15, ty = tid >> 4;
    float acc[4][6];
    #pragma unroll
    for (int i = 0; i < 4; i++)
        #pragma unroll
        for (int j = 0; j < 6; j++) acc[i][j] = 0.f;

    const int ar = tid >> 2, akc = (tid & 3) * 4;

    for (int k0 = 0; k0 < DIN; k0 += 16) {
        {
            float4 v = *(const float4*)(A + (size_t)ar * DIN + k0 + akc);
            As[akc+0][ar] = v.x; As[akc+1][ar] = v.y;
            As[akc+2][ar] = v.z; As[akc+3][ar] = v.w;
        }
        #pragma unroll
        for (int j = 0; j < 3; j++) {
            int i = tid + j * 128;
            int n = i >> 2, kc = (i & 3) * 4;
            float4 v = *(const float4*)(B + (size_t)n * DIN + k0 + kc);
            Bs[kc+0][n] = v.x; Bs[kc+1][n] = v.y;
            Bs[kc+2][n] = v.z; Bs[kc+3][n] = v.w;
        }
        __syncthreads();
        #pragma unroll
        for (int kk = 0; kk < 16; kk++) {
            float4 a4 = *(const float4*)&As[kk][ty*4];
            float ar4[4] = {a4.x, a4.y, a4.z, a4.w};
            float2 b0 = *(const float2*)&Bs[kk][tx*6];
            float2 b1 = *(const float2*)&Bs[kk][tx*6+2];
            float2 b2 = *(const float2*)&Bs[kk][tx*6+4];
            float br[6] = {b0.x, b0.y, b1.x, b1.y, b2.x, b2.y};
            #pragma unroll
            for (int i = 0; i < 4; i++)
                #pragma unroll
                for (int j = 0; j < 6; j++)
                    acc[i][j] = fmaf(ar4[i], br[j], acc[i][j]);
        }
        __syncthreads();
    }
    #pragma unroll
    for (int i = 0; i < 4; i++)
        #pragma unroll
        for (int j = 0; j < 6; j++)
            C[(size_t)(ty*4+i) * 96 + tx*6+j] = acc[i][j];
}

// ---------------- dt GEMM: softplus(xdbl[:, :64] @ dt_w^T + dt_b) ---------------
__global__ __launch_bounds__(256)
void dt_gemm(const float* __restrict__ xdblA,   // [2][ML][96]
             const float* __restrict__ w0, const float* __restrict__ w1,  // [DIN][64]
             const float* __restrict__ b0, const float* __restrict__ b1,  // [DIN]
             float* __restrict__ out)           // [2][ML][DIN]
{
    __shared__ float As[16][132];
    __shared__ float Bs[16][132];

    const int dir = blockIdx.z;
    const float* A = xdblA + (size_t)dir * ML * 96;
    const float* Bw = dir ? w1 : w0;
    const float* bias = dir ? b1 : b0;
    float* C = out + (size_t)dir * ML * DIN;

    const int tid = threadIdx.x;
    const int tx = tid & 15;
    const int ty = tid >> 4;
    const int rowBase = blockIdx.y * 128;
    const int colBase = blockIdx.x * 128;

    const int lm = tid >> 1;
    const int lk = (tid & 1) * 8;

    const float* aPtr = A + (size_t)(rowBase + lm) * 96 + lk;
    const float* bPtr = Bw + (size_t)(colBase + lm) * RDT + lk;

    float acc[8][8];
    #pragma unroll
    for (int i = 0; i < 8; i++)
        #pragma unroll
        for (int j = 0; j < 8; j++) acc[i][j] = 0.f;

    for (int k0 = 0; k0 < RDT; k0 += 16) {
        float4 a0 = *(const float4*)(aPtr + k0);
        float4 a1 = *(const float4*)(aPtr + k0 + 4);
        float4 b0v = *(const float4*)(bPtr + k0);
        float4 b1v = *(const float4*)(bPtr + k0 + 4);

        As[lk+0][lm] = a0.x; As[lk+1][lm] = a0.y; As[lk+2][lm] = a0.z; As[lk+3][lm] = a0.w;
        As[lk+4][lm] = a1.x; As[lk+5][lm] = a1.y; As[lk+6][lm] = a1.z; As[lk+7][lm] = a1.w;
        Bs[lk+0][lm] = b0v.x; Bs[lk+1][lm] = b0v.y; Bs[lk+2][lm] = b0v.z; Bs[lk+3][lm] = b0v.w;
        Bs[lk+4][lm] = b1v.x; Bs[lk+5][lm] = b1v.y; Bs[lk+6][lm] = b1v.z; Bs[lk+7][lm] = b1v.w;
        __syncthreads();

        #pragma unroll
        for (int kk = 0; kk < 16; kk++) {
            float4 ra0 = *(const float4*)&As[kk][ty * 4];
            float4 ra1 = *(const float4*)&As[kk][64 + ty * 4];
            float4 rb0 = *(const float4*)&Bs[kk][tx * 4];
            float4 rb1 = *(const float4*)&Bs[kk][64 + tx * 4];
            float ar[8] = {ra0.x, ra0.y, ra0.z, ra0.w, ra1.x, ra1.y, ra1.z, ra1.w};
            float br[8] = {rb0.x, rb0.y, rb0.z, rb0.w, rb1.x, rb1.y, rb1.z, rb1.w};
            #pragma unroll
            for (int i = 0; i < 8; i++)
                #pragma unroll
                for (int j = 0; j < 8; j++)
                    acc[i][j] = fmaf(ar[i], br[j], acc[i][j]);
        }
        __syncthreads();
    }

    #pragma unroll
    for (int i = 0; i < 8; i++) {
        int r = rowBase + ((i < 4) ? (ty * 4 + i) : (64 + ty * 4 + i - 4));
        #pragma unroll
        for (int j = 0; j < 8; j++) {
            int c = colBase + ((j < 4) ? (tx * 4 + j) : (64 + tx * 4 + j - 4));
            C[(size_t)r * DIN + c] = softplusf(acc[i][j] + bias[c]);
        }
    }
}

// ---------------- depthwise causal conv (k=4, dir-dependent taps) ---------------
__global__ void conv_kernel(const float* __restrict__ xz,   // [ML][8192]
                            const float* __restrict__ cw0, const float* __restrict__ cw1,
                            const float* __restrict__ cb0, const float* __restrict__ cb1,
                            float* __restrict__ xc)         // [2][ML][DIN]
{
    int idx = blockIdx.x * blockDim.x + threadIdx.x;
    if (idx >= 2 * ML * DIN) return;
    int dir = idx >= ML * DIN;
    int li = dir ? (idx - ML * DIN) : idx;
    int c = li & (DIN - 1);
    int r = li / DIN;
    int l = r & (LS - 1);
    int b = r >> 11;   // r / LS
    const float* cw = dir ? cw1 : cw0;
    const float* cb = dir ? cb1 : cb0;
    float acc = cb[c];
    float w0 = cw[c*4+0], w1 = cw[c*4+1], w2 = cw[c*4+2], w3 = cw[c*4+3];
    size_t colOff = (size_t)dir * 4096 + c;
    if (!dir) {
        #pragma unroll
        for (int k = 0; k < 4; k++) {
            int lp = l - 3 + k;
            if (lp >= 0) {
                float w = (k==0)?w0:(k==1)?w1:(k==2)?w2:w3;
                acc += xz[(size_t)(b * LS + lp) * 8192 + colOff] * w;
            }
        }
    } else {
        #pragma unroll
        for (int k = 0; k < 4; k++) {
            int lp = l + 3 - k;
            if (lp < LS) {
                float w = (k==0)?w0:(k==1)?w1:(k==2)?w2:w3;
                acc += xz[(size_t)(b * LS + lp) * 8192 + colOff] * w;
            }
        }
    }
    xc[(size_t)dir * ML * DIN + (size_t)r * DIN + c] = siluf(acc);
}

// ---------------- selective scan (both dirs, pipelined) -------------------------
__global__ void scan_kernel(const float* __restrict__ dt,    // [2][ML][DIN]
                            const float* __restrict__ xc,    // [2][ML][DIN]
                            const float* __restrict__ xdbl,  // [2][ML][96]
                            const float* __restrict__ xz,    // [ML][8192]
                            const float* __restrict__ A0, const float* __restrict__ A1,
                            const float* __restrict__ D0, const float* __restrict__ D1,
                            bf16* __restrict__ yhi, bf16* __restrict__ ylo)  // [2][ML][DIN]
{
    int gwarp = (blockIdx.x * blockDim.x + threadIdx.x) >> 5;
    int lane = threadIdx.x & 31;
    int half = lane >> 4;
    int s = lane & 15;
    int row = gwarp * 2 + half;            // 0 .. 2*BB*DIN-1
    if (row >= 2 * BB * DIN) return;
    int dir = row >= BB * DIN;
    int r2 = dir ? (row - BB * DIN) : row;
    int b = r2 / DIN;
    int d = r2 % DIN;

    const float* Alog = dir ? A1 : A0;
    float Av = -__expf(Alog[d * DST + s]);
    float Dd = dir ? D1[d] : D0[d];
    float h = 0.f;
    const bool w0lane = (s == 0);

    const size_t dOff = (size_t)dir * ML * DIN;
    const size_t dOff96 = (size_t)dir * ML * 96;
    const size_t base = (size_t)b * LS;
    const int l0 = dir ? (LS - 1) : 0;
    const int step = dir ? -1 : 1;

    int l = l0;
    float dtv = dt[dOff + (base + l) * DIN + d];
    float uv  = xc[dOff + (base + l) * DIN + d];
    float Bv  = xdbl[dOff96 + (base + l) * 96 + RDT + s];
    float Cv  = xdbl[dOff96 + (base + l) * 96 + RDT + DST + s];
    float zv  = w0lane ? xz[(base + l) * 8192 + dir * 4096 + 2048 + d] : 0.f;

    for (int it = 0; it < LS; it++) {
        int ln = (it + 1 < LS) ? (l + step) : l;
        float dtn = dt[dOff + (base + ln) * DIN + d];
        float un  = xc[dOff + (base + ln) * DIN + d];
        float Bn  = xdbl[dOff96 + (base + ln) * 96 + RDT + s];
        float Cn  = xdbl[dOff96 + (base + ln) * 96 + RDT + DST + s];
        float zn  = w0lane ? xz[(base + ln) * 8192 + dir * 4096 + 2048 + d] : 0.f;

        h = h * __expf(dtv * Av) + dtv * uv * Bv;
        float y = h * Cv;
        y += __shfl_xor_sync(0xffffffffu, y, 8);
        y += __shfl_xor_sync(0xffffffffu, y, 4);
        y += __shfl_xor_sync(0xffffffffu, y, 2);
        y += __shfl_xor_sync(0xffffffffu, y, 1);
        if (w0lane) {
            float yv = (y + uv * Dd) * siluf(zv);
            __nv_bfloat16 hb = __float2bfloat16(yv);
            size_t o = dOff + (base + l) * DIN + d;
            yhi[o] = hb;
            ylo[o] = __float2bfloat16(yv - __bfloat162float(hb));
        }
        l = ln; dtv = dtn; uv = un; Bv = Bn; Cv = Cn; zv = zn;
    }
}

// ---------------- residual combine ------------------------------------------------
__global__ void residual_kernel(const float* __restrict__ x,
                                const float* __restrict__ y0,
                                const float* __restrict__ y1,
                                float* __restrict__ xsum)
{
    int i = blockIdx.x * blockDim.x + threadIdx.x;
    int n = ML * DM / 4;
    if (i >= n) return;
    float4 xv = ((const float4*)x)[i];
    float4 a = ((const float4*)y0)[i];
    float4 b = ((const float4*)y1)[i];
    float4 o;
    o.x = xv.x + 0.5f * (a.x + b.x);
    o.y = xv.y + 0.5f * (a.y + b.y);
    o.z = xv.z + 0.5f * (a.z + b.z);
    o.w = xv.w + 0.5f * (a.w + b.w);
    ((float4*)xsum)[i] = o;
}

// ---------------- layernorm (1024) -> bf16 hi/lo -----------------------------------
__global__ void ln_kernel(const float* __restrict__ xin,
                          const float* __restrict__ g,
                          const float* __restrict__ bta,
                          bf16* __restrict__ outhi,
                          bf16* __restrict__ outlo)
{
    int row = blockIdx.x;
    const float4* xr = (const float4*)(xin + (size_t)row * DM);
    float4 v = xr[threadIdx.x];
    float s  = v.x + v.y + v.z + v.w;
    float sq = v.x*v.x + v.y*v.y + v.z*v.z + v.w*v.w;

    #pragma unroll
    for (int o = 16; o >= 1; o >>= 1) {
        s  += __shfl_xor_sync(0xffffffffu, s, o);
        sq += __shfl_xor_sync(0xffffffffu, sq, o);
    }
    __shared__ float ss[8], ssq[8];
    int warp = threadIdx.x >> 5, lane = threadIdx.x & 31;
    if (lane == 0) { ss[warp] = s; ssq[warp] = sq; }
    __syncthreads();
    __shared__ float sh_mean, sh_inv;
    if (threadIdx.x == 0) {
        float ts = 0.f, tq = 0.f;
        #pragma unroll
        for (int w = 0; w < 8; w++) { ts += ss[w]; tq += ssq[w]; }
        float mean = ts / DM;
        float var = tq / DM - mean * mean;
        sh_mean = mean;
        sh_inv = rsqrtf(var + 1e-5f);
    }
    __syncthreads();
    float mean = sh_mean, inv = sh_inv;
    float4 gv = ((const float4*)g)[threadIdx.x];
    float4 bv = ((const float4*)bta)[threadIdx.x];
    float o0 = (v.x - mean) * inv * gv.x + bv.x;
    float o1 = (v.y - mean) * inv * gv.y + bv.y;
    float o2 = (v.z - mean) * inv * gv.z + bv.z;
    float o3 = (v.w - mean) * inv * gv.w + bv.w;
    unsigned short h0,h1,h2,h3,l0,l1,l2,l3;
    split1(o0, h0, l0); split1(o1, h1, l1);
    split1(o2, h2, l2); split1(o3, h3, l3);
    uint2 hu, lu;
    hu.x = (uint32_t)h0 | ((uint32_t)h1 << 16);
    hu.y = (uint32_t)h2 | ((uint32_t)h3 << 16);
    lu.x = (uint32_t)l0 | ((uint32_t)l1 << 16);
    lu.y = (uint32_t)l2 | ((uint32_t)l3 << 16);
    size_t off = (size_t)row * DM + threadIdx.x * 4;
    *(uint2*)(outhi + off) = hu;
    *(uint2*)(outlo + off) = lu;
}

// ---------------- host orchestration ------------------------------------------------
extern "C" void kernel_launch(void* const* d_in, const int* in_sizes, int n_in,
                              void* d_out, int out_size)
{
    (void)in_sizes; (void)n_in; (void)out_size;

    const float* x = (const float*)d_in[0];
    const float* in_w[2]   = { (const float*)d_in[1],  (const float*)d_in[10] };
    const float* conv_w[2] = { (const float*)d_in[2],  (const float*)d_in[11] };
    const float* conv_b[2] = { (const float*)d_in[3],  (const float*)d_in[12] };
    const float* x_w[2]    = { (const float*)d_in[4],  (const float*)d_in[13] };
    const float* dt_w[2]   = { (const float*)d_in[5],  (const float*)d_in[14] };
    const float* dt_b[2]   = { (const float*)d_in[6],  (const float*)d_in[15] };
    const float* A_log[2]  = { (const float*)d_in[7],  (const float*)d_in[16] };
    const float* Dp[2]     = { (const float*)d_in[8],  (const float*)d_in[17] };
    const float* out_w[2]  = { (const float*)d_in[9],  (const float*)d_in[18] };
    const float* ff_ln_g = (const float*)d_in[19];
    const float* ff_ln_b = (const float*)d_in[20];
    const float* ff_w1   = (const float*)d_in[21];
    const float* ff_b1   = (const float*)d_in[22];
    const float* ff_w2   = (const float*)d_in[23];
    const float* ff_b2   = (const float*)d_in[24];

    float *xz, *xc, *xdbl, *dtb, *ydir, *xsum;
    bf16 *xhi, *xlo, *yhi, *ylo, *lnhi, *lnlo, *f1hi, *f1lo;
    bf16 *inwhi, *inwlo, *outwhi, *outwlo, *w1hi, *w1lo, *w2hi, *w2lo;
    cudaGetSymbolAddress((void**)&xz,   g_xz);
    cudaGetSymbolAddress((void**)&xc,   g_xc);
    cudaGetSymbolAddress((void**)&xdbl, g_xdbl);
    cudaGetSymbolAddress((void**)&dtb,  g_dt);
    cudaGetSymbolAddress((void**)&ydir, g_ydir);
    cudaGetSymbolAddress((void**)&xsum, g_xsum);
    cudaGetSymbolAddress((void**)&xhi,  g_xhi);
    cudaGetSymbolAddress((void**)&xlo,  g_xlo);
    cudaGetSymbolAddress((void**)&yhi,  g_yhi);
    cudaGetSymbolAddress((void**)&ylo,  g_ylo);
    cudaGetSymbolAddress((void**)&lnhi, g_lnhi);
    cudaGetSymbolAddress((void**)&lnlo, g_lnlo);
    cudaGetSymbolAddress((void**)&f1hi, g_f1hi);
    cudaGetSymbolAddress((void**)&f1lo, g_f1lo);
    cudaGetSymbolAddress((void**)&inwhi,  g_inwhi);
    cudaGetSymbolAddress((void**)&inwlo,  g_inwlo);
    cudaGetSymbolAddress((void**)&outwhi, g_outwhi);
    cudaGetSymbolAddress((void**)&outwlo, g_outwlo);
    cudaGetSymbolAddress((void**)&w1hi, g_w1hi);
    cudaGetSymbolAddress((void**)&w1lo, g_w1lo);
    cudaGetSymbolAddress((void**)&w2hi, g_w2hi);
    cudaGetSymbolAddress((void**)&w2lo, g_w2lo);

    cudaFuncSetAttribute(mma_gemm2, cudaFuncAttributeMaxDynamicSharedMemorySize, DSMEM2);

    const size_t szXC   = (size_t)ML * DIN;
    const size_t szYDIR = (size_t)ML * DM;
    const size_t szINW  = (size_t)2 * DIN * DM;
    const size_t szOUTW = (size_t)DM * DIN;

    dim3 blk(256);

    // launches 0-3: splits needed for in-proj + ff1
    split_kernel<<<(ML*DM/4 + 255)/256, blk>>>(x, xhi, xlo, ML*DM/4);
    split_kernel<<<((int)szINW/4 + 255)/256, blk>>>(in_w[0], inwhi,         inwlo,         (int)szINW/4);
    split_kernel<<<((int)szINW/4 + 255)/256, blk>>>(in_w[1], inwhi + szINW, inwlo + szINW, (int)szINW/4);
    split_kernel<<<(DFF*DM/4 + 255)/256, blk>>>(ff_w1, w1hi, w1lo, DFF*DM/4);

    // launch 4 (profile target): merged in-proj, M=4096, N=8192, K=1024
    mma_gemm2<<<dim3(64, 32, 1), blk, DSMEM2>>>(
        xhi, xlo, DM, inwhi, inwlo, DM,
        nullptr, nullptr, xz, nullptr, nullptr,
        8192, DM, 0, 0, 0, 0);

    // remaining splits
    split_kernel<<<((int)szOUTW/4 + 255)/256, blk>>>(out_w[0], outwhi,          outwlo,          (int)szOUTW/4);
    split_kernel<<<((int)szOUTW/4 + 255)/256, blk>>>(out_w[1], outwhi + szOUTW, outwlo + szOUTW, (int)szOUTW/4);
    split_kernel<<<(DM*DFF/4 + 255)/256, blk>>>(ff_w2, w2hi, w2lo, DM*DFF/4);

    // conv (both dirs)
    conv_kernel<<<(2*ML*DIN + 255)/256, blk>>>(xz, conv_w[0], conv_w[1],
                                               conv_b[0], conv_b[1], xc);

    // xdbl (both dirs): [2][ML][96]
    xdbl_gemm<<<dim3(ML/32, 1, 2), dim3(128)>>>(xc, x_w[0], x_w[1], xdbl);

    // dt (both dirs)
    dt_gemm<<<dim3(DIN/128, ML/128, 2), blk>>>(xdbl, dt_w[0], dt_w[1],
                                               dt_b[0], dt_b[1], dtb);

    // scan (both dirs)
    scan_kernel<<<512, blk>>>(dtb, xc, xdbl, xz, A_log[0], A_log[1],
                              Dp[0], Dp[1], yhi, ylo);

    // out-proj (both dirs via z): ydir[z] = y[z] @ out_w[z]^T
    mma_gemm2<<<dim3(8, 32, 2), blk, DSMEM2>>>(
        yhi, ylo, DIN, outwhi, outwlo, DIN,
        nullptr, nullptr, ydir, nullptr, nullptr,
        DM, DIN, 0, szXC, szOUTW, szYDIR);

    residual_kernel<<<(ML*DM/4 + 255)/256, blk>>>(x, ydir, ydir + szYDIR, xsum);
    ln_kernel<<<ML, blk>>>(xsum, ff_ln_g, ff_ln_b, lnhi, lnlo);

    // ff1 = silu(ln @ ff_w1^T + b1) -> bf16 hi/lo
    mma_gemm2<<<dim3(32, 32, 1), blk, DSMEM2>>>(
        lnhi, lnlo, DM, w1hi, w1lo, DM,
        ff_b1, nullptr, nullptr, f1hi, f1lo,
        DFF, DM, 1, 0, 0, 0);

    // out = xsum + (ff1 @ ff_w2^T + b2)
    mma_gemm2<<<dim3(8, 32, 1), blk, DSMEM2>>>(
        f1hi, f1lo, DFF, w2hi, w2lo, DFF,
        ff_b2, xsum, (float*)d_out, nullptr, nullptr,
        DM, DFF, 0, 0, 0, 0);
}

// round 6
// speedup vs baseline: 3.2121x; 1.0437x over previous
#include <cuda_runtime.h>
#include <cuda_bf16.h>
#include <math.h>
#include <stdint.h>

// Problem constants
#define BB   2
#define LS   2048
#define DM   1024
#define DIN  2048
#define DST  16
#define RDT  64
#define ML   (BB*LS)      // 4096 rows
#define DFF  (4*DM)       // 4096

typedef __nv_bfloat16 bf16;

// ---------------- scratch (device globals) -----------------------------------
// xz unified: [ML][8192], cols [dir*4096 .. +2047]=xi, [+2048..+4095]=z
__device__ __align__(256) float g_xz  [(size_t)ML * 8192];
__device__ __align__(256) float g_xc  [2u * ML * DIN];
__device__ __align__(256) float g_xdbl[2u * ML * 96];     // cols 64..95: B/C interleaved
__device__ __align__(256) float g_dtu [2u * (size_t)ML * DIN * 2];  // (dt, u) pairs
__device__ __align__(256) float g_ydir[2u * ML * DM];
__device__ __align__(256) float g_xsum[(size_t)ML * DM];

__device__ __align__(256) bf16 g_xhi [(size_t)ML * DM],  g_xlo [(size_t)ML * DM];
__device__ __align__(256) bf16 g_yhi [2u * ML * DIN],    g_ylo [2u * ML * DIN];
__device__ __align__(256) bf16 g_lnhi[(size_t)ML * DM],  g_lnlo[(size_t)ML * DM];
__device__ __align__(256) bf16 g_f1hi[(size_t)ML * DFF], g_f1lo[(size_t)ML * DFF];
__device__ __align__(256) bf16 g_inwhi [2u * 2 * DIN * DM], g_inwlo [2u * 2 * DIN * DM];
__device__ __align__(256) bf16 g_outwhi[2u * DM * DIN],     g_outwlo[2u * DM * DIN];
__device__ __align__(256) bf16 g_w1hi[(size_t)DFF * DM],  g_w1lo[(size_t)DFF * DM];
__device__ __align__(256) bf16 g_w2hi[(size_t)DM * DFF],  g_w2lo[(size_t)DM * DFF];

// ---------------- helpers ------------------------------------------------------
__device__ __forceinline__ float siluf(float v) { return v / (1.f + __expf(-v)); }
__device__ __forceinline__ float softplusf(float v) {
    return (v > 20.f) ? v : log1pf(__expf(v));
}
__device__ __forceinline__ void split1(float f, unsigned short& h, unsigned short& l) {
    __nv_bfloat16 hb = __float2bfloat16(f);
    h = __bfloat16_as_ushort(hb);
    l = __bfloat16_as_ushort(__float2bfloat16(f - __bfloat162float(hb)));
}

#define LDSM4(r0, r1, r2, r3, addr) \
    asm volatile("ldmatrix.sync.aligned.m8n8.x4.shared.b16 {%0,%1,%2,%3}, [%4];" \
        : "=r"(r0), "=r"(r1), "=r"(r2), "=r"(r3) : "r"(addr))

#define MMA16816(d, a, b0, b1) \
    asm volatile("mma.sync.aligned.m16n8k16.row.col.f32.bf16.bf16.f32 " \
        "{%0,%1,%2,%3}, {%4,%5,%6,%7}, {%8,%9}, {%0,%1,%2,%3};" \
        : "+f"((d)[0]), "+f"((d)[1]), "+f"((d)[2]), "+f"((d)[3]) \
        : "r"((a)[0]), "r"((a)[1]), "r"((a)[2]), "r"((a)[3]), "r"(b0), "r"(b1))

#define CPA16(sa, ga) \
    asm volatile("cp.async.cg.shared.global [%0], [%1], 16;" :: "r"(sa), "l"(ga))
#define CPA_COMMIT() asm volatile("cp.async.commit_group;" ::: "memory")
#define CPA_WAIT1()  asm volatile("cp.async.wait_group 1;" ::: "memory")

// ---------------- split-bf16 tensor-core GEMM (pre-split inputs) ---------------
#define KC       32
#define ARR_B    8192
#define STAGE_B  (4 * ARR_B)
#define NSTAGE   3
#define DSMEM2   (NSTAGE * STAGE_B)

__global__ __launch_bounds__(256, 2)
void mma_gemm2(const bf16* __restrict__ Ahi, const bf16* __restrict__ Alo, int lda,
               const bf16* __restrict__ Bhi, const bf16* __restrict__ Blo, int ldb,
               const float* __restrict__ bias,
               const float* __restrict__ addsrc,
               float* __restrict__ Cf,
               bf16* __restrict__ Chi, bf16* __restrict__ Clo,
               int ldc, int K, int act,
               size_t zsA, size_t zsB, size_t zsC)
{
    extern __shared__ char sm[];
    const int tid  = threadIdx.x;
    const int lane = tid & 31;
    const int wid  = tid >> 5;
    const int wm   = wid >> 2;
    const int wn   = wid & 3;
    const int rowBase = blockIdx.y * 128;
    const int colBase = blockIdx.x * 128;
    const size_t zA = (size_t)blockIdx.z * zsA;
    const size_t zB = (size_t)blockIdx.z * zsB;
    const size_t zC = (size_t)blockIdx.z * zsC;
    const uint32_t smb = (uint32_t)__cvta_generic_to_shared(sm);

    const int crow = tid >> 2;
    const int cck  = tid & 3;
    const size_t offA0 = zA + (size_t)(rowBase + crow) * lda + cck * 8;
    const size_t offA1 = zA + (size_t)(rowBase + crow + 64) * lda + cck * 8;
    const size_t offB0 = zB + (size_t)(colBase + crow) * ldb + cck * 8;
    const size_t offB1 = zB + (size_t)(colBase + crow + 64) * ldb + cck * 8;
    const uint32_t s0 = (uint32_t)crow * 64        + (uint32_t)((cck ^ ((crow >> 1) & 3)) * 16);
    const uint32_t s1 = (uint32_t)(crow + 64) * 64 + (uint32_t)((cck ^ (((crow + 64) >> 1) & 3)) * 16);

    const int laneAr = (lane & 7) + ((lane >> 3) & 1) * 8;
    const int aCk    = (lane >> 4);
    const int laneBr = (lane & 7) + ((lane >> 4) & 1) * 8;
    const int bCk    = (lane >> 3) & 1;
    uint32_t aRowB[4], aSw[4], bRowB[2], bSw[2];
    #pragma unroll
    for (int i = 0; i < 4; i++) {
        int r = wm * 64 + i * 16 + laneAr;
        aRowB[i] = (uint32_t)r * 64;
        aSw[i]   = (uint32_t)((r >> 1) & 3);
    }
    #pragma unroll
    for (int p = 0; p < 2; p++) {
        int r = wn * 32 + p * 16 + laneBr;
        bRowB[p] = (uint32_t)r * 64;
        bSw[p]   = (uint32_t)((r >> 1) & 3);
    }

    float acc[16][4];
    #pragma unroll
    for (int i = 0; i < 16; i++)
        #pragma unroll
        for (int j = 0; j < 4; j++) acc[i][j] = 0.f;

    const int nk = K / KC;

    auto issue = [&](int stg, int kt) {
        const uint32_t sb = smb + (uint32_t)stg * STAGE_B;
        const size_t ko = (size_t)kt * KC;
        CPA16(sb + 0*ARR_B + s0, Ahi + offA0 + ko);
        CPA16(sb + 0*ARR_B + s1, Ahi + offA1 + ko);
        CPA16(sb + 1*ARR_B + s0, Alo + offA0 + ko);
        CPA16(sb + 1*ARR_B + s1, Alo + offA1 + ko);
        CPA16(sb + 2*ARR_B + s0, Bhi + offB0 + ko);
        CPA16(sb + 2*ARR_B + s1, Bhi + offB1 + ko);
        CPA16(sb + 3*ARR_B + s0, Blo + offB0 + ko);
        CPA16(sb + 3*ARR_B + s1, Blo + offB1 + ko);
    };

    issue(0, 0); CPA_COMMIT();
    issue(1, 1); CPA_COMMIT();

    int stg = 0;
    for (int kt = 0; kt < nk; kt++) {
        CPA_WAIT1();
        __syncthreads();
        if (kt + 2 < nk) issue((stg + 2) % NSTAGE, kt + 2);
        CPA_COMMIT();

        const uint32_t base = smb + (uint32_t)stg * STAGE_B;
        #pragma unroll
        for (int ks = 0; ks < 2; ks++) {
            uint32_t aH[4][4], aL[4][4], bH[2][4], bL[2][4];
            #pragma unroll
            for (int i = 0; i < 4; i++)
                LDSM4(aH[i][0], aH[i][1], aH[i][2], aH[i][3],
                      base + 0*ARR_B + aRowB[i] + (((uint32_t)(ks*2 + aCk) ^ aSw[i]) * 16));
            #pragma unroll
            for (int p = 0; p < 2; p++)
                LDSM4(bH[p][0], bH[p][1], bH[p][2], bH[p][3],
                      base + 2*ARR_B + bRowB[p] + (((uint32_t)(ks*2 + bCk) ^ bSw[p]) * 16));
            #pragma unroll
            for (int i = 0; i < 4; i++)
                #pragma unroll
                for (int nt = 0; nt < 4; nt++)
                    MMA16816(acc[i*4+nt], aH[i], bH[nt>>1][(nt&1)*2], bH[nt>>1][(nt&1)*2+1]);
            #pragma unroll
            for (int i = 0; i < 4; i++)
                LDSM4(aL[i][0], aL[i][1], aL[i][2], aL[i][3],
                      base + 1*ARR_B + aRowB[i] + (((uint32_t)(ks*2 + aCk) ^ aSw[i]) * 16));
            #pragma unroll
            for (int i = 0; i < 4; i++)
                #pragma unroll
                for (int nt = 0; nt < 4; nt++)
                    MMA16816(acc[i*4+nt], aL[i], bH[nt>>1][(nt&1)*2], bH[nt>>1][(nt&1)*2+1]);
            #pragma unroll
            for (int p = 0; p < 2; p++)
                LDSM4(bL[p][0], bL[p][1], bL[p][2], bL[p][3],
                      base + 3*ARR_B + bRowB[p] + (((uint32_t)(ks*2 + bCk) ^ bSw[p]) * 16));
            #pragma unroll
            for (int i = 0; i < 4; i++)
                #pragma unroll
                for (int nt = 0; nt < 4; nt++)
                    MMA16816(acc[i*4+nt], aH[i], bL[nt>>1][(nt&1)*2], bL[nt>>1][(nt&1)*2+1]);
        }
        stg = (stg + 1) % NSTAGE;
    }

    const int erow  = wm * 64 + (lane >> 2);
    const int ecol0 = wn * 32 + (lane & 3) * 2;
    #pragma unroll
    for (int i = 0; i < 4; i++) {
        int r0 = rowBase + erow + i * 16;
        int r1 = r0 + 8;
        #pragma unroll
        for (int nt = 0; nt < 4; nt++) {
            int c = colBase + ecol0 + nt * 8;
            float v0 = acc[i*4+nt][0], v1 = acc[i*4+nt][1];
            float v2 = acc[i*4+nt][2], v3 = acc[i*4+nt][3];
            if (bias) {
                float b0 = __ldg(&bias[c]), b1 = __ldg(&bias[c+1]);
                v0 += b0; v1 += b1; v2 += b0; v3 += b1;
            }
            if (act == 1) { v0 = siluf(v0); v1 = siluf(v1); v2 = siluf(v2); v3 = siluf(v3); }
            else if (act == 2) { v0 = softplusf(v0); v1 = softplusf(v1); v2 = softplusf(v2); v3 = softplusf(v3); }
            if (addsrc) {
                v0 += addsrc[(size_t)r0 * ldc + c];
                v1 += addsrc[(size_t)r0 * ldc + c + 1];
                v2 += addsrc[(size_t)r1 * ldc + c];
                v3 += addsrc[(size_t)r1 * ldc + c + 1];
            }
            if (Cf) {
                *(float2*)&Cf[zC + (size_t)r0 * ldc + c] = make_float2(v0, v1);
                *(float2*)&Cf[zC + (size_t)r1 * ldc + c] = make_float2(v2, v3);
            } else {
                unsigned short h0,h1,h2,h3,l0,l1,l2,l3;
                split1(v0, h0, l0); split1(v1, h1, l1);
                split1(v2, h2, l2); split1(v3, h3, l3);
                *(uint32_t*)(Chi + zC + (size_t)r0 * ldc + c) = (uint32_t)h0 | ((uint32_t)h1 << 16);
                *(uint32_t*)(Clo + zC + (size_t)r0 * ldc + c) = (uint32_t)l0 | ((uint32_t)l1 << 16);
                *(uint32_t*)(Chi + zC + (size_t)r1 * ldc + c) = (uint32_t)h2 | ((uint32_t)h3 << 16);
                *(uint32_t*)(Clo + zC + (size_t)r1 * ldc + c) = (uint32_t)l2 | ((uint32_t)l3 << 16);
            }
        }
    }
}

// ---------------- fp32 -> bf16 hi/lo split --------------------------------------
__global__ void split_kernel(const float* __restrict__ in,
                             bf16* __restrict__ hi,
                             bf16* __restrict__ lo, int n4)
{
    int i = blockIdx.x * blockDim.x + threadIdx.x;
    if (i >= n4) return;
    float4 v = ((const float4*)in)[i];
    unsigned short h0,h1,h2,h3,l0,l1,l2,l3;
    split1(v.x, h0, l0); split1(v.y, h1, l1);
    split1(v.z, h2, l2); split1(v.w, h3, l3);
    uint2 hu, lu;
    hu.x = (uint32_t)h0 | ((uint32_t)h1 << 16);
    hu.y = (uint32_t)h2 | ((uint32_t)h3 << 16);
    lu.x = (uint32_t)l0 | ((uint32_t)l1 << 16);
    lu.y = (uint32_t)l2 | ((uint32_t)l3 << 16);
    *(uint2*)(hi + (size_t)i * 4) = hu;
    *(uint2*)(lo + (size_t)i * 4) = lu;
}

// ---------------- xdbl GEMM: [2][ML][96], B/C interleaved in cols 64..95 --------
__global__ __launch_bounds__(128)
void xdbl_gemm(const float* __restrict__ xcA,
               const float* __restrict__ xw0,
               const float* __restrict__ xw1,
               float* __restrict__ out)
{
    __shared__ float As[16][36];
    __shared__ float Bs[16][100];
    const int dir = blockIdx.z;
    const float* A = xcA + (size_t)dir * ML * DIN + (size_t)blockIdx.x * 32 * DIN;
    const float* B = dir ? xw1 : xw0;
    float* C = out + (size_t)dir * ML * 96 + (size_t)blockIdx.x * 32 * 96;

    const int tid = threadIdx.x;
    const int tx = tid & 15, ty = tid >> 4;
    float acc[4][6];
    #pragma unroll
    for (int i = 0; i < 4; i++)
        #pragma unroll
        for (int j = 0; j < 6; j++) acc[i][j] = 0.f;

    const int ar = tid >> 2, akc = (tid & 3) * 4;

    for (int k0 = 0; k0 < DIN; k0 += 16) {
        {
            float4 v = *(const float4*)(A + (size_t)ar * DIN + k0 + akc);
            As[akc+0][ar] = v.x; As[akc+1][ar] = v.y;
            As[akc+2][ar] = v.z; As[akc+3][ar] = v.w;
        }
        #pragma unroll
        for (int j = 0; j < 3; j++) {
            int i = tid + j * 128;
            int n = i >> 2, kc = (i & 3) * 4;
            float4 v = *(const float4*)(B + (size_t)n * DIN + k0 + kc);
            Bs[kc+0][n] = v.x; Bs[kc+1][n] = v.y;
            Bs[kc+2][n] = v.z; Bs[kc+3][n] = v.w;
        }
        __syncthreads();
        #pragma unroll
        for (int kk = 0; kk < 16; kk++) {
            float4 a4 = *(const float4*)&As[kk][ty*4];
            float ar4[4] = {a4.x, a4.y, a4.z, a4.w};
            float2 b0 = *(const float2*)&Bs[kk][tx*6];
            float2 b1 = *(const float2*)&Bs[kk][tx*6+2];
            float2 b2 = *(const float2*)&Bs[kk][tx*6+4];
            float br[6] = {b0.x, b0.y, b1.x, b1.y, b2.x, b2.y};
            #pragma unroll
            for (int i = 0; i < 4; i++)
                #pragma unroll
                for (int j = 0; j < 6; j++)
                    acc[i][j] = fmaf(ar4[i], br[j], acc[i][j]);
        }
        __syncthreads();
    }
    #pragma unroll
    for (int i = 0; i < 4; i++)
        #pragma unroll
        for (int j = 0; j < 6; j++) {
            int c = tx*6 + j;
            // remap: B cols 64..79 -> 64+2s, C cols 80..95 -> 64+2s+1
            int cw = (c < 64) ? c : ((c < 80) ? (64 + 2*(c - 64)) : (65 + 2*(c - 80)));
            C[(size_t)(ty*4+i) * 96 + cw] = acc[i][j];
        }
}

// ---------------- dt GEMM -> (dt, u) float2 pairs --------------------------------
__global__ __launch_bounds__(256)
void dt_gemm(const float* __restrict__ xdblA,
             const float* __restrict__ xcA,
             const float* __restrict__ w0, const float* __restrict__ w1,
             const float* __restrict__ b0, const float* __restrict__ b1,
             float* __restrict__ out)          // [2][ML][DIN][2]
{
    __shared__ float As[16][132];
    __shared__ float Bs[16][132];

    const int dir = blockIdx.z;
    const float* A = xdblA + (size_t)dir * ML * 96;
    const float* xcD = xcA + (size_t)dir * ML * DIN;
    const float* Bw = dir ? w1 : w0;
    const float* bias = dir ? b1 : b0;
    float* C = out + (size_t)dir * ML * DIN * 2;

    const int tid = threadIdx.x;
    const int tx = tid & 15;
    const int ty = tid >> 4;
    const int rowBase = blockIdx.y * 128;
    const int colBase = blockIdx.x * 128;

    const int lm = tid >> 1;
    const int lk = (tid & 1) * 8;

    const float* aPtr = A + (size_t)(rowBase + lm) * 96 + lk;
    const float* bPtr = Bw + (size_t)(colBase + lm) * RDT + lk;

    float acc[8][8];
    #pragma unroll
    for (int i = 0; i < 8; i++)
        #pragma unroll
        for (int j = 0; j < 8; j++) acc[i][j] = 0.f;

    for (int k0 = 0; k0 < RDT; k0 += 16) {
        float4 a0 = *(const float4*)(aPtr + k0);
        float4 a1 = *(const float4*)(aPtr + k0 + 4);
        float4 b0v = *(const float4*)(bPtr + k0);
        float4 b1v = *(const float4*)(bPtr + k0 + 4);

        As[lk+0][lm] = a0.x; As[lk+1][lm] = a0.y; As[lk+2][lm] = a0.z; As[lk+3][lm] = a0.w;
        As[lk+4][lm] = a1.x; As[lk+5][lm] = a1.y; As[lk+6][lm] = a1.z; As[lk+7][lm] = a1.w;
        Bs[lk+0][lm] = b0v.x; Bs[lk+1][lm] = b0v.y; Bs[lk+2][lm] = b0v.z; Bs[lk+3][lm] = b0v.w;
        Bs[lk+4][lm] = b1v.x; Bs[lk+5][lm] = b1v.y; Bs[lk+6][lm] = b1v.z; Bs[lk+7][lm] = b1v.w;
        __syncthreads();

        #pragma unroll
        for (int kk = 0; kk < 16; kk++) {
            float4 ra0 = *(const float4*)&As[kk][ty * 4];
            float4 ra1 = *(const float4*)&As[kk][64 + ty * 4];
            float4 rb0 = *(const float4*)&Bs[kk][tx * 4];
            float4 rb1 = *(const float4*)&Bs[kk][64 + tx * 4];
            float ar[8] = {ra0.x, ra0.y, ra0.z, ra0.w, ra1.x, ra1.y, ra1.z, ra1.w};
            float br[8] = {rb0.x, rb0.y, rb0.z, rb0.w, rb1.x, rb1.y, rb1.z, rb1.w};
            #pragma unroll
            for (int i = 0; i < 8; i++)
                #pragma unroll
                for (int j = 0; j < 8; j++)
                    acc[i][j] = fmaf(ar[i], br[j], acc[i][j]);
        }
        __syncthreads();
    }

    #pragma unroll
    for (int i = 0; i < 8; i++) {
        int r = rowBase + ((i < 4) ? (ty * 4 + i) : (64 + ty * 4 + i - 4));
        #pragma unroll
        for (int j = 0; j < 8; j++) {
            int c = colBase + ((j < 4) ? (tx * 4 + j) : (64 + tx * 4 + j - 4));
            float dtv = softplusf(acc[i][j] + bias[c]);
            float uv  = xcD[(size_t)r * DIN + c];
            *(float2*)&C[((size_t)r * DIN + c) * 2] = make_float2(dtv, uv);
        }
    }
}

// ---------------- depthwise causal conv (k=4, dir-dependent taps) ---------------
__global__ void conv_kernel(const float* __restrict__ xz,
                            const float* __restrict__ cw0, const float* __restrict__ cw1,
                            const float* __restrict__ cb0, const float* __restrict__ cb1,
                            float* __restrict__ xc)
{
    int idx = blockIdx.x * blockDim.x + threadIdx.x;
    if (idx >= 2 * ML * DIN) return;
    int dir = idx >= ML * DIN;
    int li = dir ? (idx - ML * DIN) : idx;
    int c = li & (DIN - 1);
    int r = li / DIN;
    int l = r & (LS - 1);
    int b = r >> 11;
    const float* cw = dir ? cw1 : cw0;
    const float* cb = dir ? cb1 : cb0;
    float acc = cb[c];
    float w0 = cw[c*4+0], w1 = cw[c*4+1], w2 = cw[c*4+2], w3 = cw[c*4+3];
    size_t colOff = (size_t)dir * 4096 + c;
    if (!dir) {
        #pragma unroll
        for (int k = 0; k < 4; k++) {
            int lp = l - 3 + k;
            if (lp >= 0) {
                float w = (k==0)?w0:(k==1)?w1:(k==2)?w2:w3;
                acc += xz[(size_t)(b * LS + lp) * 8192 + colOff] * w;
            }
        }
    } else {
        #pragma unroll
        for (int k = 0; k < 4; k++) {
            int lp = l + 3 - k;
            if (lp < LS) {
                float w = (k==0)?w0:(k==1)?w1:(k==2)?w2:w3;
                acc += xz[(size_t)(b * LS + lp) * 8192 + colOff] * w;
            }
        }
    }
    xc[(size_t)dir * ML * DIN + (size_t)r * DIN + c] = siluf(acc);
}

// ---------------- selective scan (packed operands) -------------------------------
__global__ void scan_kernel(const float* __restrict__ dtu,   // [2][ML][DIN][2]
                            const float* __restrict__ xdbl,  // [2][ML][96] (B/C paired)
                            const float* __restrict__ xz,    // [ML][8192]
                            const float* __restrict__ A0, const float* __restrict__ A1,
                            const float* __restrict__ D0, const float* __restrict__ D1,
                            bf16* __restrict__ yhi, bf16* __restrict__ ylo)
{
    int gwarp = (blockIdx.x * blockDim.x + threadIdx.x) >> 5;
    int lane = threadIdx.x & 31;
    int half = lane >> 4;
    int s = lane & 15;
    int row = gwarp * 2 + half;
    if (row >= 2 * BB * DIN) return;
    int dir = row >= BB * DIN;
    int r2 = dir ? (row - BB * DIN) : row;
    int b = r2 / DIN;
    int d = r2 % DIN;

    const float* Alog = dir ? A1 : A0;
    float Av = -__expf(Alog[d * DST + s]);
    float Dd = dir ? D1[d] : D0[d];
    float h = 0.f;
    const bool w0lane = (s == 0);

    const size_t base = (size_t)b * LS;
    const int l0 = dir ? (LS - 1) : 0;
    const int step = dir ? -1 : 1;

    // incremental pointers
    const float* pDtu = dtu + ((size_t)dir * ML * DIN + (base + l0) * DIN + d) * 2;
    const float* pBC  = xdbl + (size_t)dir * ML * 96 + (base + l0) * 96 + RDT + 2 * s;
    const float* pZ   = xz + (base + l0) * 8192 + (size_t)dir * 4096 + 2048 + d;
    bf16* pYhi = yhi + (size_t)dir * ML * DIN + (base + l0) * DIN + d;
    bf16* pYlo = ylo + (size_t)dir * ML * DIN + (base + l0) * DIN + d;
    const ptrdiff_t sDtu = (ptrdiff_t)step * DIN * 2;
    const ptrdiff_t sBC  = (ptrdiff_t)step * 96;
    const ptrdiff_t sZ   = (ptrdiff_t)step * 8192;
    const ptrdiff_t sY   = (ptrdiff_t)step * DIN;

    float2 du = *(const float2*)pDtu;
    float2 bc = *(const float2*)pBC;
    float zv  = w0lane ? *pZ : 0.f;

    for (int it = 0; it < LS; it++) {
        const bool more = (it + 1 < LS);
        float2 dun = more ? *(const float2*)(pDtu + sDtu) : du;
        float2 bcn = more ? *(const float2*)(pBC + sBC)   : bc;
        float zn   = (w0lane && more) ? *(pZ + sZ) : zv;

        h = h * __expf(du.x * Av) + du.x * du.y * bc.x;
        float y = h * bc.y;
        y += __shfl_xor_sync(0xffffffffu, y, 8);
        y += __shfl_xor_sync(0xffffffffu, y, 4);
        y += __shfl_xor_sync(0xffffffffu, y, 2);
        y += __shfl_xor_sync(0xffffffffu, y, 1);
        if (w0lane) {
            float yv = (y + du.y * Dd) * siluf(zv);
            __nv_bfloat16 hb = __float2bfloat16(yv);
            *pYhi = hb;
            *pYlo = __float2bfloat16(yv - __bfloat162float(hb));
            pYhi += sY; pYlo += sY;
        }
        pDtu += sDtu; pBC += sBC; pZ += sZ;
        du = dun; bc = bcn; zv = zn;
    }
}

// ---------------- fused residual + layernorm -> xsum + bf16 hi/lo ----------------
__global__ void resln_kernel(const float* __restrict__ x,
                             const float* __restrict__ y0,
                             const float* __restrict__ y1,
                             const float* __restrict__ g,
                             const float* __restrict__ bta,
                             float* __restrict__ xsum,
                             bf16* __restrict__ outhi,
                             bf16* __restrict__ outlo)
{
    int row = blockIdx.x;
    size_t off4 = (size_t)row * (DM / 4) + threadIdx.x;
    float4 xv = ((const float4*)x)[off4];
    float4 a = ((const float4*)y0)[off4];
    float4 b = ((const float4*)y1)[off4];
    float4 v;
    v.x = xv.x + 0.5f * (a.x + b.x);
    v.y = xv.y + 0.5f * (a.y + b.y);
    v.z = xv.z + 0.5f * (a.z + b.z);
    v.w = xv.w + 0.5f * (a.w + b.w);
    ((float4*)xsum)[off4] = v;

    float s  = v.x + v.y + v.z + v.w;
    float sq = v.x*v.x + v.y*v.y + v.z*v.z + v.w*v.w;
    #pragma unroll
    for (int o = 16; o >= 1; o >>= 1) {
        s  += __shfl_xor_sync(0xffffffffu, s, o);
        sq += __shfl_xor_sync(0xffffffffu, sq, o);
    }
    __shared__ float ss[8], ssq[8];
    int warp = threadIdx.x >> 5, lane = threadIdx.x & 31;
    if (lane == 0) { ss[warp] = s; ssq[warp] = sq; }
    __syncthreads();
    __shared__ float sh_mean, sh_inv;
    if (threadIdx.x == 0) {
        float ts = 0.f, tq = 0.f;
        #pragma unroll
        for (int w = 0; w < 8; w++) { ts += ss[w]; tq += ssq[w]; }
        float mean = ts / DM;
        float var = tq / DM - mean * mean;
        sh_mean = mean;
        sh_inv = rsqrtf(var + 1e-5f);
    }
    __syncthreads();
    float mean = sh_mean, inv = sh_inv;
    float4 gv = ((const float4*)g)[threadIdx.x];
    float4 bv = ((const float4*)bta)[threadIdx.x];
    float o0 = (v.x - mean) * inv * gv.x + bv.x;
    float o1 = (v.y - mean) * inv * gv.y + bv.y;
    float o2 = (v.z - mean) * inv * gv.z + bv.z;
    float o3 = (v.w - mean) * inv * gv.w + bv.w;
    unsigned short h0,h1,h2,h3,l0,l1,l2,l3;
    split1(o0, h0, l0); split1(o1, h1, l1);
    split1(o2, h2, l2); split1(o3, h3, l3);
    uint2 hu, lu;
    hu.x = (uint32_t)h0 | ((uint32_t)h1 << 16);
    hu.y = (uint32_t)h2 | ((uint32_t)h3 << 16);
    lu.x = (uint32_t)l0 | ((uint32_t)l1 << 16);
    lu.y = (uint32_t)l2 | ((uint32_t)l3 << 16);
    size_t off = (size_t)row * DM + threadIdx.x * 4;
    *(uint2*)(outhi + off) = hu;
    *(uint2*)(outlo + off) = lu;
}

// ---------------- host orchestration ----------------------------------------------
extern "C" void kernel_launch(void* const* d_in, const int* in_sizes, int n_in,
                              void* d_out, int out_size)
{
    (void)in_sizes; (void)n_in; (void)out_size;

    const float* x = (const float*)d_in[0];
    const float* in_w[2]   = { (const float*)d_in[1],  (const float*)d_in[10] };
    const float* conv_w[2] = { (const float*)d_in[2],  (const float*)d_in[11] };
    const float* conv_b[2] = { (const float*)d_in[3],  (const float*)d_in[12] };
    const float* x_w[2]    = { (const float*)d_in[4],  (const float*)d_in[13] };
    const float* dt_w[2]   = { (const float*)d_in[5],  (const float*)d_in[14] };
    const float* dt_b[2]   = { (const float*)d_in[6],  (const float*)d_in[15] };
    const float* A_log[2]  = { (const float*)d_in[7],  (const float*)d_in[16] };
    const float* Dp[2]     = { (const float*)d_in[8],  (const float*)d_in[17] };
    const float* out_w[2]  = { (const float*)d_in[9],  (const float*)d_in[18] };
    const float* ff_ln_g = (const float*)d_in[19];
    const float* ff_ln_b = (const float*)d_in[20];
    const float* ff_w1   = (const float*)d_in[21];
    const float* ff_b1   = (const float*)d_in[22];
    const float* ff_w2   = (const float*)d_in[23];
    const float* ff_b2   = (const float*)d_in[24];

    float *xz, *xc, *xdbl, *dtu, *ydir, *xsum;
    bf16 *xhi, *xlo, *yhi, *ylo, *lnhi, *lnlo, *f1hi, *f1lo;
    bf16 *inwhi, *inwlo, *outwhi, *outwlo, *w1hi, *w1lo, *w2hi, *w2lo;
    cudaGetSymbolAddress((void**)&xz,   g_xz);
    cudaGetSymbolAddress((void**)&xc,   g_xc);
    cudaGetSymbolAddress((void**)&xdbl, g_xdbl);
    cudaGetSymbolAddress((void**)&dtu,  g_dtu);
    cudaGetSymbolAddress((void**)&ydir, g_ydir);
    cudaGetSymbolAddress((void**)&xsum, g_xsum);
    cudaGetSymbolAddress((void**)&xhi,  g_xhi);
    cudaGetSymbolAddress((void**)&xlo,  g_xlo);
    cudaGetSymbolAddress((void**)&yhi,  g_yhi);
    cudaGetSymbolAddress((void**)&ylo,  g_ylo);
    cudaGetSymbolAddress((void**)&lnhi, g_lnhi);
    cudaGetSymbolAddress((void**)&lnlo, g_lnlo);
    cudaGetSymbolAddress((void**)&f1hi, g_f1hi);
    cudaGetSymbolAddress((void**)&f1lo, g_f1lo);
    cudaGetSymbolAddress((void**)&inwhi,  g_inwhi);
    cudaGetSymbolAddress((void**)&inwlo,  g_inwlo);
    cudaGetSymbolAddress((void**)&outwhi, g_outwhi);
    cudaGetSymbolAddress((void**)&outwlo, g_outwlo);
    cudaGetSymbolAddress((void**)&w1hi, g_w1hi);
    cudaGetSymbolAddress((void**)&w1lo, g_w1lo);
    cudaGetSymbolAddress((void**)&w2hi, g_w2hi);
    cudaGetSymbolAddress((void**)&w2lo, g_w2lo);

    cudaFuncSetAttribute(mma_gemm2, cudaFuncAttributeMaxDynamicSharedMemorySize, DSMEM2);

    const size_t szXC   = (size_t)ML * DIN;
    const size_t szYDIR = (size_t)ML * DM;
    const size_t szINW  = (size_t)2 * DIN * DM;
    const size_t szOUTW = (size_t)DM * DIN;

    dim3 blk(256);

    // idx 0-2: splits needed for in-proj
    split_kernel<<<(ML*DM/4 + 255)/256, blk>>>(x, xhi, xlo, ML*DM/4);
    split_kernel<<<((int)szINW/4 + 255)/256, blk>>>(in_w[0], inwhi,         inwlo,         (int)szINW/4);
    split_kernel<<<((int)szINW/4 + 255)/256, blk>>>(in_w[1], inwhi + szINW, inwlo + szINW, (int)szINW/4);

    // idx 3 (ncu profiles my 4th launch): merged in-proj, M=4096, N=8192, K=1024
    mma_gemm2<<<dim3(64, 32, 1), blk, DSMEM2>>>(
        xhi, xlo, DM, inwhi, inwlo, DM,
        nullptr, nullptr, xz, nullptr, nullptr,
        8192, DM, 0, 0, 0, 0);

    // remaining splits
    split_kernel<<<(DFF*DM/4 + 255)/256, blk>>>(ff_w1, w1hi, w1lo, DFF*DM/4);
    split_kernel<<<((int)szOUTW/4 + 255)/256, blk>>>(out_w[0], outwhi,          outwlo,          (int)szOUTW/4);
    split_kernel<<<((int)szOUTW/4 + 255)/256, blk>>>(out_w[1], outwhi + szOUTW, outwlo + szOUTW, (int)szOUTW/4);
    split_kernel<<<(DM*DFF/4 + 255)/256, blk>>>(ff_w2, w2hi, w2lo, DM*DFF/4);

    // conv (both dirs)
    conv_kernel<<<(2*ML*DIN + 255)/256, blk>>>(xz, conv_w[0], conv_w[1],
                                               conv_b[0], conv_b[1], xc);

    // xdbl (both dirs), B/C interleaved
    xdbl_gemm<<<dim3(ML/32, 1, 2), dim3(128)>>>(xc, x_w[0], x_w[1], xdbl);

    // dt (both dirs) -> (dt, u) pairs
    dt_gemm<<<dim3(DIN/128, ML/128, 2), blk>>>(xdbl, xc, dt_w[0], dt_w[1],
                                               dt_b[0], dt_b[1], dtu);

    // scan (both dirs)
    scan_kernel<<<512, blk>>>(dtu, xdbl, xz, A_log[0], A_log[1],
                              Dp[0], Dp[1], yhi, ylo);

    // out-proj (both dirs via z)
    mma_gemm2<<<dim3(8, 32, 2), blk, DSMEM2>>>(
        yhi, ylo, DIN, outwhi, outwlo, DIN,
        nullptr, nullptr, ydir, nullptr, nullptr,
        DM, DIN, 0, szXC, szOUTW, szYDIR);

    // fused residual + LN
    resln_kernel<<<ML, blk>>>(x, ydir, ydir + szYDIR, ff_ln_g, ff_ln_b,
                              xsum, lnhi, lnlo);

    // ff1 = silu(ln @ ff_w1^T + b1) -> bf16 hi/lo
    mma_gemm2<<<dim3(32, 32, 1), blk, DSMEM2>>>(
        lnhi, lnlo, DM, w1hi, w1lo, DM,
        ff_b1, nullptr, nullptr, f1hi, f1lo,
        DFF, DM, 1, 0, 0, 0);

    // out = xsum + (ff1 @ ff_w2^T + b2)
    mma_gemm2<<<dim3(8, 32, 1), blk, DSMEM2>>>(
        f1hi, f1lo, DFF, w2hi, w2lo, DFF,
        ff_b2, xsum, (float*)d_out, nullptr, nullptr,
        DM, DFF, 0, 0, 0, 0);
}